// round 7
// baseline (speedup 1.0000x reference)
#include <cuda_runtime.h>

#define NT     512
#define TLEN   512
#define LD     36     // padded leading dim, 32-col matrices
#define LDA    68     // augmented GJ matrix leading dim
#define LDCT   20     // C-transpose leading dim
#define LDK    20     // KT2 leading dim

#define CONST_FLOATS 20480
#define CH_FLOATS    15184
// ---- per-chain smem offsets (floats) ----
#define C_A    0       // 32xLD   A_t
#define C_ATR  1152    // 32xLD   A_t^T
#define C_CM   2304    // 16xLD   C_t        (backward: Ytr 32xLD, spans C_CM+C_CTR)
#define C_CTR  2880    // 32xLDCT C_t^T
#define C_ZC   3520    // 32xLD   covariance state
#define C_TMP  4672    // 32xLD   B mixture / D
#define C_PP   5824    // 32xLD   P_pred / W
#define C_CPM  6976    // 16xLD   M = C*P
#define C_AUG0 7552    // 32xLDA
#define C_AUG1 9728    // 32xLDA
#define C_KT2  11904   // 32xLDK  Kg^T transposed (row i, col r)
#define C_FCS  12544   // 2 x 32xLD filtered cov (parity)
#define C_FMS  14848   // 2 x 32
#define C_ZM   14912   // 32
#define C_ZM2  14944   // 32
#define C_AL   14976   // 2 x 8
#define C_SU   14992   // 2 x 32
#define C_SA   15056   // 2 x 16
#define C_AP   15088   // 16
#define C_DZ   15104   // 32
#define C_QD   15136   // 32
#define C_RD   15168   // 16
#define SMEM_FLOATS (CONST_FLOATS + 2 * CH_FLOATS)

__device__ __forceinline__ float4 f4fma(float s, float4 b, float4 a) {  // a + s*b
    return make_float4(fmaf(s,b.x,a.x), fmaf(s,b.y,a.y), fmaf(s,b.z,a.z), fmaf(s,b.w,a.w));
}
__device__ __forceinline__ float4 f4scale(float4 a, float s) {
    return make_float4(a.x*s, a.y*s, a.z*s, a.w*s);
}
#define FMA4S(acc, s, b)                                                      \
    acc.x = fmaf((s), (b).x, acc.x); acc.y = fmaf((s), (b).y, acc.y);         \
    acc.z = fmaf((s), (b).z, acc.z); acc.w = fmaf((s), (b).w, acc.w);
#define FMA4L(s4, m4, v4)                                                     \
    s4.x = fmaf(m4.x, v4.x, s4.x); s4.y = fmaf(m4.y, v4.y, s4.y);             \
    s4.z = fmaf(m4.z, v4.z, s4.z); s4.w = fmaf(m4.w, v4.w, s4.w);

// C[i][j..j+3] = rowA[0..31] . matB[0..31][j..j+3], dual accumulators
__device__ __forceinline__ float4 mm4(const float* __restrict__ rowA,
                                      const float* __restrict__ matB,
                                      const int ldB, const int jj) {
    float4 a0 = make_float4(0.f,0.f,0.f,0.f);
    float4 a1 = make_float4(0.f,0.f,0.f,0.f);
    #pragma unroll
    for (int k0 = 0; k0 < 32; k0 += 8) {
        float4 x = *(const float4*)(rowA + k0);
        float4 y = *(const float4*)(rowA + k0 + 4);
        const float* Bp = matB + k0 * ldB + jj;
        float4 b;
        b = *(const float4*)(Bp);           FMA4S(a0, x.x, b);
        b = *(const float4*)(Bp + ldB);     FMA4S(a1, x.y, b);
        b = *(const float4*)(Bp + 2*ldB);   FMA4S(a0, x.z, b);
        b = *(const float4*)(Bp + 3*ldB);   FMA4S(a1, x.w, b);
        b = *(const float4*)(Bp + 4*ldB);   FMA4S(a0, y.x, b);
        b = *(const float4*)(Bp + 5*ldB);   FMA4S(a1, y.y, b);
        b = *(const float4*)(Bp + 6*ldB);   FMA4S(a0, y.z, b);
        b = *(const float4*)(Bp + 7*ldB);   FMA4S(a1, y.w, b);
    }
    return make_float4(a0.x + a1.x, a0.y + a1.y, a0.z + a1.z, a0.w + a1.w);
}

// ---- 4-pivot Gauss-Jordan block state ----
struct GJ4 {
    float inv0, inv1, inv2, inv3;
    float P10, P20, P30, a21, a31, a32;
    float c0, c1, c2, c3;
    int p0, gi;
};
__device__ __forceinline__ GJ4 gj4_pre(const float* __restrict__ Asrc, int gi, int p0) {
    GJ4 s; s.p0 = p0; s.gi = gi;
    const float4 R0 = *(const float4*)(Asrc + (p0+0)*LDA + p0);
    const float4 R1 = *(const float4*)(Asrc + (p0+1)*LDA + p0);
    const float4 R2 = *(const float4*)(Asrc + (p0+2)*LDA + p0);
    const float4 R3 = *(const float4*)(Asrc + (p0+3)*LDA + p0);
    const float4 Ci = *(const float4*)(Asrc + gi*LDA + p0);
    s.inv0 = __fdividef(1.f, R0.x);
    float u01 = R0.y*s.inv0, u02 = R0.z*s.inv0, u03 = R0.w*s.inv0;
    s.P10 = R1.x;
    float a11 = fmaf(-R1.x, u01, R1.y);  s.inv1 = __fdividef(1.f, a11);
    float a12 = fmaf(-R1.x, u02, R1.z), a13 = fmaf(-R1.x, u03, R1.w);
    float v12 = a12*s.inv1, v13 = a13*s.inv1;
    s.P20 = R2.x;
    s.a21 = fmaf(-R2.x, u01, R2.y);
    float a22 = fmaf(-s.a21, v12, fmaf(-R2.x, u02, R2.z));
    s.inv2 = __fdividef(1.f, a22);
    float a23 = fmaf(-s.a21, v13, fmaf(-R2.x, u03, R2.w));
    float w23 = a23*s.inv2;
    s.P30 = R3.x;
    s.a31 = fmaf(-R3.x, u01, R3.y);
    s.a32 = fmaf(-s.a31, v12, fmaf(-R3.x, u02, R3.z));
    float a33 = fmaf(-s.a32, w23, fmaf(-s.a31, v13, fmaf(-R3.x, u03, R3.w)));
    s.inv3 = __fdividef(1.f, a33);
    s.c0 = Ci.x;
    s.c1 = (gi==p0)   ? u01 : fmaf(-s.c0, u01, Ci.y);
    float c2t = (gi==p0)   ? u02 : fmaf(-s.c0, u02, Ci.z);
    s.c2 = (gi==p0+1) ? v12 : fmaf(-s.c1, v12, c2t);
    float c3t = (gi==p0)   ? u03 : fmaf(-s.c0, u03, Ci.w);
    float c3u = (gi==p0+1) ? v13 : fmaf(-s.c1, v13, c3t);
    s.c3 = (gi==p0+2) ? w23 : fmaf(-s.c2, w23, c3u);
    return s;
}
__device__ __forceinline__ float4 gj4_col4(const GJ4& s, const float* __restrict__ Asrc, int jj) {
    const int p0 = s.p0, gi = s.gi;
    float4 m0 = *(const float4*)(Asrc + (p0+0)*LDA + jj);
    float4 m1 = *(const float4*)(Asrc + (p0+1)*LDA + jj);
    float4 m2 = *(const float4*)(Asrc + (p0+2)*LDA + jj);
    float4 m3 = *(const float4*)(Asrc + (p0+3)*LDA + jj);
    float4 mi = *(const float4*)(Asrc + gi*LDA + jj);
    float4 r0 = f4scale(m0, s.inv0);
    float4 E  = (gi==p0)   ? r0 : f4fma(-s.c0, r0, mi);
    float4 t1 = f4fma(-s.P10, r0, m1);
    float4 r1 = f4scale(t1, s.inv1);
    E = (gi==p0+1) ? r1 : f4fma(-s.c1, r1, E);
    float4 t2 = f4fma(-s.a21, r1, f4fma(-s.P20, r0, m2));
    float4 r2 = f4scale(t2, s.inv2);
    E = (gi==p0+2) ? r2 : f4fma(-s.c2, r2, E);
    float4 t3 = f4fma(-s.a32, r2, f4fma(-s.a31, r1, f4fma(-s.P30, r0, m3)));
    float4 r3 = f4scale(t3, s.inv3);
    E = (gi==p0+3) ? r3 : f4fma(-s.c3, r3, E);
    return E;
}

__global__ __launch_bounds__(NT, 1)
void lgssm_kernel(const float* __restrict__ g_a,   const float* __restrict__ g_alpha,
                  const float* __restrict__ g_u,   const float* __restrict__ g_A,
                  const float* __restrict__ g_B,   const float* __restrict__ g_C,
                  const float* __restrict__ g_lQ,  const float* __restrict__ g_lR,
                  const float* __restrict__ g_z0m, const float* __restrict__ g_z0lv,
                  float* __restrict__ out)
{
    extern __shared__ float sh[];
    float* sAm = sh;            // 8192
    float* sBm = sh + 8192;     // 8192
    float* sCm = sh + 16384;    // 4096

    const int tid = threadIdx.x;
    const int c   = tid >> 8;          // chain 0/1
    const int ct  = tid & 255;         // thread within chain
    const int b2  = blockIdx.x * 2 + c;

    float* chsh = sh + CONST_FLOATS + c * CH_FLOATS;
    float* pA   = chsh + C_A;
    float* pAtr = chsh + C_ATR;
    float* pCm  = chsh + C_CM;
    float* pCtr = chsh + C_CTR;
    float* Ytr  = chsh + C_CM;     // backward alias (1152 <= 1216)
    float* zc   = chsh + C_ZC;
    float* tmpM = chsh + C_TMP;
    float* pPp  = chsh + C_PP;
    float* pCPm = chsh + C_CPM;
    float* aug0 = chsh + C_AUG0;
    float* aug1 = chsh + C_AUG1;
    float* KT2  = chsh + C_KT2;
    float* fcS  = chsh + C_FCS;
    float* fmS  = chsh + C_FMS;
    float* zm   = chsh + C_ZM;
    float* zm2  = chsh + C_ZM2;
    float* alB  = chsh + C_AL;
    float* suB  = chsh + C_SU;
    float* saB  = chsh + C_SA;
    float* apred= chsh + C_AP;
    float* dz   = chsh + C_DZ;
    float* qd   = chsh + C_QD;
    float* rd   = chsh + C_RD;

    const int i4 = ct >> 3;            // 0..31
    const int j4 = (ct & 7) << 2;      // 0,4..28

    // ---- preload constants (block-wide) ----
    for (int idx = tid; idx < 8192; idx += NT) sAm[idx] = g_A[idx];
    for (int idx = tid; idx < 8192; idx += NT) sBm[idx] = g_B[idx];
    for (int idx = tid; idx < 4096; idx += NT) sCm[idx] = g_C[idx];
    // ---- per-chain init ----
    {
        const size_t ib0 = (size_t)b2 * TLEN;
        if (ct < 8)  alB[ct] = g_alpha[ib0 * 8  + ct];
        if (ct < 32) suB[ct] = g_u    [ib0 * 32 + ct];
        if (ct < 16) saB[ct] = g_a    [ib0 * 16 + ct];
        if (ct < 32) zm[ct]  = g_z0m[ct];
        if (ct < 32) qd[ct]  = expf(g_lQ[ct]);
        if (ct < 16) rd[ct]  = expf(g_lR[ct]);
        float4 v = make_float4(0.f, 0.f, 0.f, 0.f);
        int d = i4 - j4;
        if (d >= 0 && d < 4) ((float*)&v)[d] = expf(g_z0lv[i4]);
        *(float4*)(zc + i4 * LD + j4) = v;
    }
    __syncthreads();

    // =============== FORWARD FILTER ===============
    #pragma unroll 1
    for (int t = 0; t < TLEN; ++t) {
        const size_t ib = (size_t)b2 * TLEN + t;
        const int pb = t & 1, nb = pb ^ 1;
        const bool hasnext = (t + 1 < TLEN);

        float pfa = 0.f, pfu = 0.f, pfo = 0.f;
        if (hasnext) {
            if (ct < 8)  pfa = g_alpha[(ib + 1) * 8  + ct];
            if (ct < 32) pfu = g_u    [(ib + 1) * 32 + ct];
            if (ct < 16) pfo = g_a    [(ib + 1) * 16 + ct];
        }

        // ---- P0: mixtures A, A^T, B(tmpM), C, C^T ----
        {
            const float* al = alB + pb * 8;
            float4 aa = make_float4(0.f,0.f,0.f,0.f);
            float4 bb = make_float4(0.f,0.f,0.f,0.f);
            #pragma unroll
            for (int k = 0; k < 8; ++k) {
                const float w = al[k];
                float4 m = *(const float4*)(sAm + k * 1024 + i4 * 32 + j4);
                FMA4S(aa, w, m);
                m = *(const float4*)(sBm + k * 1024 + i4 * 32 + j4);
                FMA4S(bb, w, m);
            }
            *(float4*)(pA + i4 * LD + j4) = aa;
            pAtr[(j4+0)*LD + i4] = aa.x; pAtr[(j4+1)*LD + i4] = aa.y;
            pAtr[(j4+2)*LD + i4] = aa.z; pAtr[(j4+3)*LD + i4] = aa.w;
            *(float4*)(tmpM + i4 * LD + j4) = bb;
            if (ct < 128) {
                float4 cc = make_float4(0.f,0.f,0.f,0.f);
                #pragma unroll
                for (int k = 0; k < 8; ++k) {
                    const float w = al[k];
                    float4 m = *(const float4*)(sCm + k * 512 + i4 * 32 + j4);
                    FMA4S(cc, w, m);
                }
                *(float4*)(pCm + i4 * LD + j4) = cc;
                pCtr[(j4+0)*LDCT + i4] = cc.x; pCtr[(j4+1)*LDCT + i4] = cc.y;
                pCtr[(j4+2)*LDCT + i4] = cc.z; pCtr[(j4+3)*LDCT + i4] = cc.w;
            }
        }
        __syncthreads();

        if (t > 0) {
            // ---- P1: Pp = A zc ; zm2 = A zm + B u (last warp extra) ----
            {
                float4 acc = mm4(pA + i4 * LD, zc, LD, j4);
                *(float4*)(pPp + i4 * LD + j4) = acc;
            }
            if (ct >= 224) {
                const int i = ct - 224;
                const float* su = suB + pb * 32;
                float4 s4 = make_float4(0.f,0.f,0.f,0.f);
                #pragma unroll
                for (int k0 = 0; k0 < 32; k0 += 4) {
                    float4 m4 = *(const float4*)(tmpM + i * LD + k0);
                    float4 v4 = *(const float4*)(su + k0);
                    FMA4L(s4, m4, v4);
                    m4 = *(const float4*)(pA + i * LD + k0);
                    v4 = *(const float4*)(zm + k0);
                    FMA4L(s4, m4, v4);
                }
                zm2[i] = (s4.x + s4.y) + (s4.z + s4.w);
            }
            __syncthreads();
            // ---- P2: zc = Pp A^T + Q ; zm = zm2 ----
            {
                float4 acc = mm4(pPp + i4 * LD, pAtr, LD, j4);
                int d = i4 - j4;
                if (d >= 0 && d < 4) ((float*)&acc)[d] += qd[i4];
                *(float4*)(zc + i4 * LD + j4) = acc;
            }
            if (ct < 32) zm[ct] = zm2[ct];
            __syncthreads();
        }

        // ---- P3: M = C zc (128 thr) ; apred = C zm (16 thr) ----
        if (ct < 128) {
            float4 acc = mm4(pCm + i4 * LD, zc, LD, j4);
            *(float4*)(pCPm + i4 * LD + j4) = acc;
        } else if (ct >= 240) {
            const int i = ct - 240;
            float4 s4 = make_float4(0.f,0.f,0.f,0.f);
            #pragma unroll
            for (int k0 = 0; k0 < 32; k0 += 4) {
                float4 m4 = *(const float4*)(pCm + i * LD + k0);
                float4 v4 = *(const float4*)(zm + k0);
                FMA4L(s4, m4, v4);
            }
            apred[i] = (s4.x + s4.y) + (s4.z + s4.w);
        }
        __syncthreads();

        // ---- P4: aug0 = [S | M], dz = a - apred; store prefetched inputs ----
        if (ct < 64) {
            const int i = ct >> 2, j0 = (ct & 3) << 2;
            float4 acc = mm4(pCPm + i * LD, pCtr, LDCT, j0);
            int d = i - j0;
            if (d >= 0 && d < 4) ((float*)&acc)[d] += rd[i];
            *(float4*)(aug0 + i * LDA + j0) = acc;
        } else if (ct < 192) {
            const int idx = ct - 64;
            const int i = idx >> 3, j0 = (idx & 7) << 2;
            *(float4*)(aug0 + i * LDA + 16 + j0) = *(const float4*)(pCPm + i * LD + j0);
        } else if (ct < 208) {
            const int j = ct - 192;
            dz[j] = saB[pb * 16 + j] - apred[j];
        }
        if (hasnext) {
            if (ct < 8)  alB[nb * 8  + ct] = pfa;
            if (ct < 32) suB[nb * 32 + ct] = pfu;
            if (ct < 16) saB[nb * 16 + ct] = pfo;
        }
        __syncthreads();

        // ---- GJ: 16 pivots, 4 per phase, float4 columns (4 barriers) ----
        {
            const int gi   = ct >> 4;       // 0..15
            const int gcol = ct & 15;       // group; active if < 12
            const int jj   = gcol << 2;
            float* Asrc = aug0; float* Adst = aug1;
            #pragma unroll
            for (int pp = 0; pp < 4; ++pp) {
                if (gcol < 12) {
                    GJ4 s = gj4_pre(Asrc, gi, pp << 2);
                    float4 E = gj4_col4(s, Asrc, jj);
                    *(float4*)(Adst + gi * LDA + jj) = E;
                    if (pp == 3 && jj >= 16) {
                        KT2[(jj-16+0)*LDK + gi] = E.x;
                        KT2[(jj-16+1)*LDK + gi] = E.y;
                        KT2[(jj-16+2)*LDK + gi] = E.z;
                        KT2[(jj-16+3)*LDK + gi] = E.w;
                    }
                }
                float* tsw = Asrc; Asrc = Adst; Adst = tsw;
                __syncthreads();
            }
        }
        // KT2[i][r] = Kg^T[r][i]

        // ---- P13: measurement update + filtered output ----
        {
            const size_t ob = ib * 2112;
            if (ct < 32) {
                float4 s4 = make_float4(0.f,0.f,0.f,0.f);
                #pragma unroll
                for (int r0 = 0; r0 < 16; r0 += 4) {
                    float4 k4 = *(const float4*)(KT2 + ct * LDK + r0);
                    float4 d4 = *(const float4*)(dz + r0);
                    FMA4L(s4, k4, d4);
                }
                float nm = zm[ct] + (s4.x + s4.y) + (s4.z + s4.w);
                zm[ct] = nm;
                out[ob + ct] = nm;
                if (t == TLEN - 1) out[ob + 1056 + ct] = nm;
            }
            float4 acc = *(const float4*)(zc + i4 * LD + j4);
            #pragma unroll
            for (int r0 = 0; r0 < 16; r0 += 4) {
                float4 k4 = *(const float4*)(KT2 + i4 * LDK + r0);
                float4 m;
                m = *(const float4*)(pCPm + (r0+0)*LD + j4); acc = f4fma(-k4.x, m, acc);
                m = *(const float4*)(pCPm + (r0+1)*LD + j4); acc = f4fma(-k4.y, m, acc);
                m = *(const float4*)(pCPm + (r0+2)*LD + j4); acc = f4fma(-k4.z, m, acc);
                m = *(const float4*)(pCPm + (r0+3)*LD + j4); acc = f4fma(-k4.w, m, acc);
            }
            *(float4*)(zc + i4 * LD + j4) = acc;
            *(float4*)(out + ob + 32 + i4 * 32 + j4) = acc;
            if (t == TLEN - 1) *(float4*)(out + ob + 1088 + i4 * 32 + j4) = acc;
        }
        // no trailing barrier: next P0 writes disjoint smem; P0-end barrier orders zm/zc
    }

    // =============== BACKWARD RTS SMOOTHER ===============
    {   // preload buffers for first backward iteration (t = TLEN-2)
        const size_t ibl = (size_t)b2 * TLEN + (TLEN - 1);
        const size_t ibp = (size_t)b2 * TLEN + (TLEN - 2);
        if (ct < 8)  alB[8  + ct] = g_alpha[ibl * 8  + ct];   // mb0 = 1
        if (ct < 32) suB[32 + ct] = g_u    [ibl * 32 + ct];
        if (ct < 32) fmS[ct]      = out[ibp * 2112 + ct];     // pb0 = 0
        *(float4*)(fcS + i4 * LD + j4) =
            *(const float4*)(out + ibp * 2112 + 32 + i4 * 32 + j4);
    }
    __syncthreads();

    #pragma unroll 1
    for (int t = TLEN - 2; t >= 0; --t) {
        const size_t ib = (size_t)b2 * TLEN + t;
        const size_t ob = ib * 2112;
        const int pb = t & 1;          // fm/fc parity
        const int mb = (t + 1) & 1;    // alpha/u parity
        const bool hasprev = (t > 0);
        float* fcSp = fcS + pb * (32 * LD);
        float* fmSp = fmS + pb * 32;

        float pfa = 0.f, pfu = 0.f, pfm = 0.f;
        float4 pfc = make_float4(0.f,0.f,0.f,0.f);
        if (ct < 8)  pfa = g_alpha[ib * 8  + ct];
        if (ct < 32) pfu = g_u    [ib * 32 + ct];
        if (hasprev) {
            const size_t obp = (ib - 1) * 2112;
            if (ct < 32) pfm = out[obp + ct];
            pfc = *(const float4*)(out + obp + 32 + i4 * 32 + j4);
        }

        // ---- P0: mixtures A, A^T, B(tmpM) for step t+1 ----
        {
            const float* al = alB + mb * 8;
            float4 aa = make_float4(0.f,0.f,0.f,0.f);
            float4 bb = make_float4(0.f,0.f,0.f,0.f);
            #pragma unroll
            for (int k = 0; k < 8; ++k) {
                const float w = al[k];
                float4 m = *(const float4*)(sAm + k * 1024 + i4 * 32 + j4);
                FMA4S(aa, w, m);
                m = *(const float4*)(sBm + k * 1024 + i4 * 32 + j4);
                FMA4S(bb, w, m);
            }
            *(float4*)(pA + i4 * LD + j4) = aa;
            pAtr[(j4+0)*LD + i4] = aa.x; pAtr[(j4+1)*LD + i4] = aa.y;
            pAtr[(j4+2)*LD + i4] = aa.z; pAtr[(j4+3)*LD + i4] = aa.w;
            *(float4*)(tmpM + i4 * LD + j4) = bb;
        }
        __syncthreads();

        // ---- P1: N = A fc -> aug0 cols 32..63 ; dz (last warp extra) ----
        {
            float4 acc = mm4(pA + i4 * LD, fcSp, LD, j4);
            *(float4*)(aug0 + i4 * LDA + 32 + j4) = acc;
        }
        if (ct >= 224) {
            const int i = ct - 224;
            const float* su = suB + mb * 32;
            float4 s4 = make_float4(0.f,0.f,0.f,0.f);
            #pragma unroll
            for (int k0 = 0; k0 < 32; k0 += 4) {
                float4 m4 = *(const float4*)(tmpM + i * LD + k0);
                float4 v4 = *(const float4*)(su + k0);
                FMA4L(s4, m4, v4);
                m4 = *(const float4*)(pA + i * LD + k0);
                v4 = *(const float4*)(fmSp + k0);
                FMA4L(s4, m4, v4);
            }
            dz[i] = zm[i] - ((s4.x + s4.y) + (s4.z + s4.w));
        }
        __syncthreads();

        // ---- P2: P_pred = N A^T + Q -> pPp and aug0 left; store prefetch ----
        {
            float4 acc = mm4(aug0 + i4 * LDA + 32, pAtr, LD, j4);
            int d = i4 - j4;
            if (d >= 0 && d < 4) ((float*)&acc)[d] += qd[i4];
            *(float4*)(pPp + i4 * LD + j4) = acc;
            *(float4*)(aug0 + i4 * LDA + j4) = acc;
        }
        if (ct < 8)  alB[pb * 8  + ct] = pfa;
        if (ct < 32) suB[pb * 32 + ct] = pfu;
        if (hasprev) {
            if (ct < 32) fmS[mb * 32 + ct] = pfm;
            *(float4*)(fcS + mb * (32 * LD) + i4 * LD + j4) = pfc;
        }
        __syncthreads();

        // ---- GJ: 32 pivots, 4 per phase, float4 columns (8 barriers) ----
        {
            const int gi  = ct >> 3;        // 0..31
            const int g   = ct & 7;
            const int jjA = g << 2;         // 0..28
            const int jjB = (g + 8) << 2;   // 32..60
            float* Asrc = aug0; float* Adst = aug1;
            #pragma unroll
            for (int pp = 0; pp < 8; ++pp) {
                GJ4 s = gj4_pre(Asrc, gi, pp << 2);
                float4 EA = gj4_col4(s, Asrc, jjA);
                float4 EB = gj4_col4(s, Asrc, jjB);
                *(float4*)(Adst + gi * LDA + jjA) = EA;
                *(float4*)(Adst + gi * LDA + jjB) = EB;
                if (pp == 7) {
                    Ytr[(jjB-32+0)*LD + gi] = EB.x;
                    Ytr[(jjB-32+1)*LD + gi] = EB.y;
                    Ytr[(jjB-32+2)*LD + gi] = EB.z;
                    Ytr[(jjB-32+3)*LD + gi] = EB.w;
                }
                float* tsw = Asrc; Asrc = Adst; Adst = tsw;
                __syncthreads();
            }
        }
        // Y in aug0 cols 32..63 ; Ytr[i][k] = Y[k][i]

        // ---- P19: zs = fm + Y^T dz ; D = Ps - Ppred -> tmpM ----
        if (ct < 32) {
            float4 s4 = make_float4(0.f,0.f,0.f,0.f);
            #pragma unroll
            for (int k0 = 0; k0 < 32; k0 += 4) {
                float4 y4 = *(const float4*)(Ytr + ct * LD + k0);
                float4 d4 = *(const float4*)(dz + k0);
                FMA4L(s4, y4, d4);
            }
            float nm = fmSp[ct] + (s4.x + s4.y) + (s4.z + s4.w);
            zm[ct] = nm;
            out[ob + 1056 + ct] = nm;
        }
        {
            float4 a  = *(const float4*)(zc  + i4 * LD + j4);
            float4 p4 = *(const float4*)(pPp + i4 * LD + j4);
            a.x -= p4.x; a.y -= p4.y; a.z -= p4.z; a.w -= p4.w;
            *(float4*)(tmpM + i4 * LD + j4) = a;
        }
        __syncthreads();

        // ---- P20: W = D Y -> pPp ----
        {
            float4 acc = mm4(tmpM + i4 * LD, aug0 + 32, LDA, j4);
            *(float4*)(pPp + i4 * LD + j4) = acc;
        }
        __syncthreads();

        // ---- P21: Ps = fc + Ytr W -> zc, write sc ----
        {
            float4 w = mm4(Ytr + i4 * LD, pPp, LD, j4);
            float4 acc = *(const float4*)(fcSp + i4 * LD + j4);
            acc.x += w.x; acc.y += w.y; acc.z += w.z; acc.w += w.w;
            *(float4*)(zc + i4 * LD + j4) = acc;
            *(float4*)(out + ob + 1088 + i4 * 32 + j4) = acc;
        }
        // no trailing barrier: next P0 writes pA/pAtr/tmpM (tmpM last read P20,
        // ordered by P20-end barrier); Ytr rewritten only in next GJ last phase.
    }
}

extern "C" void kernel_launch(void* const* d_in, const int* in_sizes, int n_in,
                              void* d_out, int out_size) {
    const float* g_a    = (const float*)d_in[0];
    const float* g_alpha= (const float*)d_in[1];
    const float* g_u    = (const float*)d_in[2];
    const float* g_A    = (const float*)d_in[3];
    const float* g_B    = (const float*)d_in[4];
    const float* g_C    = (const float*)d_in[5];
    const float* g_lQ   = (const float*)d_in[6];
    const float* g_lR   = (const float*)d_in[7];
    const float* g_z0m  = (const float*)d_in[8];
    const float* g_z0lv = (const float*)d_in[9];
    float* out = (float*)d_out;
    int B = in_sizes[0] / (TLEN * 16);
    int grid = B / 2;
    size_t smem = SMEM_FLOATS * sizeof(float);
    cudaFuncSetAttribute(lgssm_kernel, cudaFuncAttributeMaxDynamicSharedMemorySize, (int)smem);
    lgssm_kernel<<<grid, NT, smem>>>(g_a, g_alpha, g_u, g_A, g_B, g_C,
                                     g_lQ, g_lR, g_z0m, g_z0lv, out);
}

// round 8
// speedup vs baseline: 1.7587x; 1.7587x over previous
#include <cuda_runtime.h>

#define NT     512
#define TLEN   512
#define LD     36     // padded leading dim, 32-col matrices
#define LDA    68     // augmented GJ matrix leading dim
#define LDCT   20     // C-transpose leading dim
#define LDK    20     // KT2 leading dim

// ---- shared memory layout (float offsets) ----
#define O_SAM  0       // 8*32*32 A components
#define O_SBM  8192    // 8*32*32 B components
#define O_SCM  16384   // 8*16*32 C components
#define O_A    20480   // 32xLD   A_t
#define O_ATR  21632   // 32xLD   A_t^T
#define O_CM   22784   // 16xLD   C_t   (backward alias: Ytr 32xLD spans CM+CTR)
#define O_CTR  23360   // 32xLDCT C_t^T
#define O_ZC   24000   // 32xLD   covariance state
#define O_TMP  25152   // 32xLD   B mixture
#define O_PP   26304   // 32xLD   P_pred (fwd scratch / bwd Ppred)
#define O_CPM  27456   // 16xLD   M = C*P
#define O_AUG0 28032   // 32xLDA  GJ buffer 0
#define O_AUG1 30208   // 32xLDA  GJ buffer 1 (bwd: W after GJ)
#define O_KT2  32384   // 32xLDK  Kg^T transposed
#define O_FCS  33024   // 2 x 32xLD filtered cov (parity)
#define O_FMS  35328   // 2 x 32
#define O_ZM   35392   // 32
#define O_ZM2  35424   // 32
#define O_AL   35456   // 2 x 8
#define O_SU   35472   // 2 x 32
#define O_SA   35536   // 2 x 16
#define O_AP   35568   // 16
#define O_DZ   35584   // 32
#define O_QD   35616   // 32
#define O_RD   35648   // 16
#define SMEM_FLOATS 35664

__device__ __forceinline__ float4 f4fma(float s, float4 b, float4 a) {  // a + s*b
    return make_float4(fmaf(s,b.x,a.x), fmaf(s,b.y,a.y), fmaf(s,b.z,a.z), fmaf(s,b.w,a.w));
}
__device__ __forceinline__ float4 f4scale(float4 a, float s) {
    return make_float4(a.x*s, a.y*s, a.z*s, a.w*s);
}
#define FMA4S(acc, s, b)                                                      \
    acc.x = fmaf((s), (b).x, acc.x); acc.y = fmaf((s), (b).y, acc.y);         \
    acc.z = fmaf((s), (b).z, acc.z); acc.w = fmaf((s), (b).w, acc.w);
#define FMA4L(s4, m4, v4)                                                     \
    s4.x = fmaf(m4.x, v4.x, s4.x); s4.y = fmaf(m4.y, v4.y, s4.y);             \
    s4.z = fmaf(m4.z, v4.z, s4.z); s4.w = fmaf(m4.w, v4.w, s4.w);

// C[i][j..j+3] = rowA[0..31] . matB[0..31][j..j+3], dual accumulators
__device__ __forceinline__ float4 mm4(const float* __restrict__ rowA,
                                      const float* __restrict__ matB,
                                      const int ldB, const int jj) {
    float4 a0 = make_float4(0.f,0.f,0.f,0.f);
    float4 a1 = make_float4(0.f,0.f,0.f,0.f);
    #pragma unroll
    for (int k0 = 0; k0 < 32; k0 += 8) {
        float4 x = *(const float4*)(rowA + k0);
        float4 y = *(const float4*)(rowA + k0 + 4);
        const float* Bp = matB + k0 * ldB + jj;
        float4 b;
        b = *(const float4*)(Bp);           FMA4S(a0, x.x, b);
        b = *(const float4*)(Bp + ldB);     FMA4S(a1, x.y, b);
        b = *(const float4*)(Bp + 2*ldB);   FMA4S(a0, x.z, b);
        b = *(const float4*)(Bp + 3*ldB);   FMA4S(a1, x.w, b);
        b = *(const float4*)(Bp + 4*ldB);   FMA4S(a0, y.x, b);
        b = *(const float4*)(Bp + 5*ldB);   FMA4S(a1, y.y, b);
        b = *(const float4*)(Bp + 6*ldB);   FMA4S(a0, y.z, b);
        b = *(const float4*)(Bp + 7*ldB);   FMA4S(a1, y.w, b);
    }
    return make_float4(a0.x + a1.x, a0.y + a1.y, a0.z + a1.z, a0.w + a1.w);
}

// C[i][j..j+3] = (rowA - rowS)[0..31] . matB[0..31][j..j+3]
__device__ __forceinline__ float4 mmdiff4(const float* __restrict__ rowA,
                                          const float* __restrict__ rowS,
                                          const float* __restrict__ matB,
                                          const int ldB, const int jj) {
    float4 a0 = make_float4(0.f,0.f,0.f,0.f);
    float4 a1 = make_float4(0.f,0.f,0.f,0.f);
    #pragma unroll
    for (int k0 = 0; k0 < 32; k0 += 8) {
        float4 xa = *(const float4*)(rowA + k0);
        float4 xs = *(const float4*)(rowS + k0);
        float4 ya = *(const float4*)(rowA + k0 + 4);
        float4 ys = *(const float4*)(rowS + k0 + 4);
        float4 x = make_float4(xa.x-xs.x, xa.y-xs.y, xa.z-xs.z, xa.w-xs.w);
        float4 y = make_float4(ya.x-ys.x, ya.y-ys.y, ya.z-ys.z, ya.w-ys.w);
        const float* Bp = matB + k0 * ldB + jj;
        float4 b;
        b = *(const float4*)(Bp);           FMA4S(a0, x.x, b);
        b = *(const float4*)(Bp + ldB);     FMA4S(a1, x.y, b);
        b = *(const float4*)(Bp + 2*ldB);   FMA4S(a0, x.z, b);
        b = *(const float4*)(Bp + 3*ldB);   FMA4S(a1, x.w, b);
        b = *(const float4*)(Bp + 4*ldB);   FMA4S(a0, y.x, b);
        b = *(const float4*)(Bp + 5*ldB);   FMA4S(a1, y.y, b);
        b = *(const float4*)(Bp + 6*ldB);   FMA4S(a0, y.z, b);
        b = *(const float4*)(Bp + 7*ldB);   FMA4S(a1, y.w, b);
    }
    return make_float4(a0.x + a1.x, a0.y + a1.y, a0.z + a1.z, a0.w + a1.w);
}

// ---- 4-pivot Gauss-Jordan block state ----
struct GJ4 {
    float inv0, inv1, inv2, inv3;
    float P10, P20, P30, a21, a31, a32;
    float c0, c1, c2, c3;
    int p0, gi;
};
__device__ __forceinline__ GJ4 gj4_pre(const float* __restrict__ Asrc, int gi, int p0) {
    GJ4 s; s.p0 = p0; s.gi = gi;
    const float4 R0 = *(const float4*)(Asrc + (p0+0)*LDA + p0);
    const float4 R1 = *(const float4*)(Asrc + (p0+1)*LDA + p0);
    const float4 R2 = *(const float4*)(Asrc + (p0+2)*LDA + p0);
    const float4 R3 = *(const float4*)(Asrc + (p0+3)*LDA + p0);
    const float4 Ci = *(const float4*)(Asrc + gi*LDA + p0);
    s.inv0 = __fdividef(1.f, R0.x);
    float u01 = R0.y*s.inv0, u02 = R0.z*s.inv0, u03 = R0.w*s.inv0;
    s.P10 = R1.x;
    float a11 = fmaf(-R1.x, u01, R1.y);  s.inv1 = __fdividef(1.f, a11);
    float a12 = fmaf(-R1.x, u02, R1.z), a13 = fmaf(-R1.x, u03, R1.w);
    float v12 = a12*s.inv1, v13 = a13*s.inv1;
    s.P20 = R2.x;
    s.a21 = fmaf(-R2.x, u01, R2.y);
    float a22 = fmaf(-s.a21, v12, fmaf(-R2.x, u02, R2.z));
    s.inv2 = __fdividef(1.f, a22);
    float a23 = fmaf(-s.a21, v13, fmaf(-R2.x, u03, R2.w));
    float w23 = a23*s.inv2;
    s.P30 = R3.x;
    s.a31 = fmaf(-R3.x, u01, R3.y);
    s.a32 = fmaf(-s.a31, v12, fmaf(-R3.x, u02, R3.z));
    float a33 = fmaf(-s.a32, w23, fmaf(-s.a31, v13, fmaf(-R3.x, u03, R3.w)));
    s.inv3 = __fdividef(1.f, a33);
    s.c0 = Ci.x;
    s.c1 = (gi==p0)   ? u01 : fmaf(-s.c0, u01, Ci.y);
    float c2t = (gi==p0)   ? u02 : fmaf(-s.c0, u02, Ci.z);
    s.c2 = (gi==p0+1) ? v12 : fmaf(-s.c1, v12, c2t);
    float c3t = (gi==p0)   ? u03 : fmaf(-s.c0, u03, Ci.w);
    float c3u = (gi==p0+1) ? v13 : fmaf(-s.c1, v13, c3t);
    s.c3 = (gi==p0+2) ? w23 : fmaf(-s.c2, w23, c3u);
    return s;
}
__device__ __forceinline__ float4 gj4_col4(const GJ4& s, const float* __restrict__ Asrc, int jj) {
    const int p0 = s.p0, gi = s.gi;
    float4 m0 = *(const float4*)(Asrc + (p0+0)*LDA + jj);
    float4 m1 = *(const float4*)(Asrc + (p0+1)*LDA + jj);
    float4 m2 = *(const float4*)(Asrc + (p0+2)*LDA + jj);
    float4 m3 = *(const float4*)(Asrc + (p0+3)*LDA + jj);
    float4 mi = *(const float4*)(Asrc + gi*LDA + jj);
    float4 r0 = f4scale(m0, s.inv0);
    float4 E  = (gi==p0)   ? r0 : f4fma(-s.c0, r0, mi);
    float4 t1 = f4fma(-s.P10, r0, m1);
    float4 r1 = f4scale(t1, s.inv1);
    E = (gi==p0+1) ? r1 : f4fma(-s.c1, r1, E);
    float4 t2 = f4fma(-s.a21, r1, f4fma(-s.P20, r0, m2));
    float4 r2 = f4scale(t2, s.inv2);
    E = (gi==p0+2) ? r2 : f4fma(-s.c2, r2, E);
    float4 t3 = f4fma(-s.a32, r2, f4fma(-s.a31, r1, f4fma(-s.P30, r0, m3)));
    float4 r3 = f4scale(t3, s.inv3);
    E = (gi==p0+3) ? r3 : f4fma(-s.c3, r3, E);
    return E;
}

__global__ __launch_bounds__(NT, 1)
void lgssm_kernel(const float* __restrict__ g_a,   const float* __restrict__ g_alpha,
                  const float* __restrict__ g_u,   const float* __restrict__ g_A,
                  const float* __restrict__ g_B,   const float* __restrict__ g_C,
                  const float* __restrict__ g_lQ,  const float* __restrict__ g_lR,
                  const float* __restrict__ g_z0m, const float* __restrict__ g_z0lv,
                  float* __restrict__ out)
{
    extern __shared__ float sh[];
    float* sAm  = sh + O_SAM;
    float* sBm  = sh + O_SBM;
    float* sCm  = sh + O_SCM;
    float* pA   = sh + O_A;
    float* pAtr = sh + O_ATR;
    float* pCm  = sh + O_CM;
    float* pCtr = sh + O_CTR;
    float* Ytr  = sh + O_CM;   // backward alias
    float* zc   = sh + O_ZC;
    float* tmpM = sh + O_TMP;
    float* pPp  = sh + O_PP;
    float* pCPm = sh + O_CPM;
    float* aug0 = sh + O_AUG0;
    float* aug1 = sh + O_AUG1;
    float* KT2  = sh + O_KT2;
    float* fcS  = sh + O_FCS;
    float* fmS  = sh + O_FMS;
    float* zm   = sh + O_ZM;
    float* zm2  = sh + O_ZM2;
    float* alB  = sh + O_AL;
    float* suB  = sh + O_SU;
    float* saB  = sh + O_SA;
    float* apred= sh + O_AP;
    float* dz   = sh + O_DZ;
    float* qd   = sh + O_QD;
    float* rd   = sh + O_RD;

    const int tid = threadIdx.x;
    const int b   = blockIdx.x;
    const int i4  = tid >> 3;          // 0..31 for tid<256 (float4 maps)
    const int j4  = (tid & 7) << 2;    // 0,4..28

    // ---- preload constants, noise diagonals, t=0 inputs, init state ----
    for (int idx = tid; idx < 8192; idx += NT) sAm[idx] = g_A[idx];
    for (int idx = tid; idx < 8192; idx += NT) sBm[idx] = g_B[idx];
    for (int idx = tid; idx < 4096; idx += NT) sCm[idx] = g_C[idx];
    if (tid < 32) qd[tid] = expf(g_lQ[tid]);
    if (tid < 16) rd[tid] = expf(g_lR[tid]);
    {
        const size_t ib0 = (size_t)b * TLEN;
        if (tid < 8)  alB[tid] = g_alpha[ib0 * 8  + tid];
        if (tid < 32) suB[tid] = g_u    [ib0 * 32 + tid];
        if (tid < 16) saB[tid] = g_a    [ib0 * 16 + tid];
        if (tid < 32) zm[tid]  = g_z0m[tid];
        if (tid < 256) {
            float4 v = make_float4(0.f, 0.f, 0.f, 0.f);
            int d = i4 - j4;
            if (d >= 0 && d < 4) ((float*)&v)[d] = expf(g_z0lv[i4]);
            *(float4*)(zc + i4 * LD + j4) = v;
        }
    }
    __syncthreads();

    // =============== FORWARD FILTER ===============
    #pragma unroll 1
    for (int t = 0; t < TLEN; ++t) {
        const size_t ib = (size_t)b * TLEN + t;
        const int pb = t & 1, nb = pb ^ 1;
        const bool hasnext = (t + 1 < TLEN);

        float pfa = 0.f, pfu = 0.f, pfo = 0.f;
        if (hasnext) {
            if (tid < 8)  pfa = g_alpha[(ib + 1) * 8  + tid];
            if (tid < 32) pfu = g_u    [(ib + 1) * 32 + tid];
            if (tid < 16) pfo = g_a    [(ib + 1) * 16 + tid];
        }

        // ---- P0: mixtures A, A^T, B(tmpM), C, C^T (256 thr) ----
        if (tid < 256) {
            const float* al = alB + pb * 8;
            float4 aa = make_float4(0.f,0.f,0.f,0.f);
            float4 bb = make_float4(0.f,0.f,0.f,0.f);
            #pragma unroll
            for (int k = 0; k < 8; ++k) {
                const float w = al[k];
                float4 m = *(const float4*)(sAm + k * 1024 + i4 * 32 + j4);
                FMA4S(aa, w, m);
                m = *(const float4*)(sBm + k * 1024 + i4 * 32 + j4);
                FMA4S(bb, w, m);
            }
            *(float4*)(pA + i4 * LD + j4) = aa;
            pAtr[(j4+0)*LD + i4] = aa.x; pAtr[(j4+1)*LD + i4] = aa.y;
            pAtr[(j4+2)*LD + i4] = aa.z; pAtr[(j4+3)*LD + i4] = aa.w;
            *(float4*)(tmpM + i4 * LD + j4) = bb;
        } else {
            const int ii = i4 - 32;   // 0..31 -> C rows 0..15 use half
            if (ii < 16) {
                const float* al = alB + pb * 8;
                float4 cc = make_float4(0.f,0.f,0.f,0.f);
                #pragma unroll
                for (int k = 0; k < 8; ++k) {
                    const float w = al[k];
                    float4 m = *(const float4*)(sCm + k * 512 + ii * 32 + j4);
                    FMA4S(cc, w, m);
                }
                *(float4*)(pCm + ii * LD + j4) = cc;
                pCtr[(j4+0)*LDCT + ii] = cc.x; pCtr[(j4+1)*LDCT + ii] = cc.y;
                pCtr[(j4+2)*LDCT + ii] = cc.z; pCtr[(j4+3)*LDCT + ii] = cc.w;
            }
        }
        __syncthreads();

        if (t > 0) {
            // ---- P1: Pp = A zc (256 thr) ; zm2 = A zm + B u (warp 15) ----
            if (tid < 256) {
                float4 acc = mm4(pA + i4 * LD, zc, LD, j4);
                *(float4*)(pPp + i4 * LD + j4) = acc;
            } else if (tid >= 480) {
                const int i = tid - 480;
                const float* su = suB + pb * 32;
                float4 s4 = make_float4(0.f,0.f,0.f,0.f);
                #pragma unroll
                for (int k0 = 0; k0 < 32; k0 += 4) {
                    float4 m4 = *(const float4*)(tmpM + i * LD + k0);
                    float4 v4 = *(const float4*)(su + k0);
                    FMA4L(s4, m4, v4);
                    m4 = *(const float4*)(pA + i * LD + k0);
                    v4 = *(const float4*)(zm + k0);
                    FMA4L(s4, m4, v4);
                }
                zm2[i] = (s4.x + s4.y) + (s4.z + s4.w);
            }
            __syncthreads();
            // ---- P2: zc = Pp A^T + Q ; zm = zm2 ----
            if (tid < 256) {
                float4 acc = mm4(pPp + i4 * LD, pAtr, LD, j4);
                int d = i4 - j4;
                if (d >= 0 && d < 4) ((float*)&acc)[d] += qd[i4];
                *(float4*)(zc + i4 * LD + j4) = acc;
            } else if (tid >= 480) {
                zm[tid - 480] = zm2[tid - 480];
            }
            __syncthreads();
        }

        // ---- P3: M = C zc -> pCPm AND aug0 cols 16..47 ; apred ----
        if (tid < 128) {
            const int i = tid >> 3;   // 0..15
            float4 acc = mm4(pCm + i * LD, zc, LD, j4);
            *(float4*)(pCPm + i * LD + j4) = acc;
            *(float4*)(aug0 + i * LDA + 16 + j4) = acc;
        } else if (tid >= 496) {
            const int i = tid - 496;
            float4 s4 = make_float4(0.f,0.f,0.f,0.f);
            #pragma unroll
            for (int k0 = 0; k0 < 32; k0 += 4) {
                float4 m4 = *(const float4*)(pCm + i * LD + k0);
                float4 v4 = *(const float4*)(zm + k0);
                FMA4L(s4, m4, v4);
            }
            apred[i] = (s4.x + s4.y) + (s4.z + s4.w);
        }
        __syncthreads();

        // ---- P4: S -> aug0 cols 0..15 ; dz ; store prefetched inputs ----
        if (tid < 64) {
            const int i = tid >> 2, j0 = (tid & 3) << 2;
            float4 acc = mm4(pCPm + i * LD, pCtr, LDCT, j0);
            int d = i - j0;
            if (d >= 0 && d < 4) ((float*)&acc)[d] += rd[i];
            *(float4*)(aug0 + i * LDA + j0) = acc;
        } else if (tid >= 128 && tid < 144) {
            const int j = tid - 128;
            dz[j] = saB[pb * 16 + j] - apred[j];
        }
        if (hasnext) {
            if (tid < 8)  alB[nb * 8  + tid] = pfa;
            if (tid < 32) suB[nb * 32 + tid] = pfu;
            if (tid < 16) saB[nb * 16 + tid] = pfo;
        }
        __syncthreads();

        // ---- GJ fwd: 16 pivots, 4/phase, 12 col-groups x 16 rows (192 thr) ----
        {
            const int gi   = tid & 15;
            const int gcol = tid >> 4;      // active < 12
            const int jj   = gcol << 2;
            float* Asrc = aug0; float* Adst = aug1;
            #pragma unroll
            for (int pp = 0; pp < 4; ++pp) {
                if (gcol < 12 && (pp < 3 || jj >= 16)) {
                    GJ4 s = gj4_pre(Asrc, gi, pp << 2);
                    float4 E = gj4_col4(s, Asrc, jj);
                    if (pp < 3) {
                        *(float4*)(Adst + gi * LDA + jj) = E;
                    } else {
                        KT2[(jj-16+0)*LDK + gi] = E.x;
                        KT2[(jj-16+1)*LDK + gi] = E.y;
                        KT2[(jj-16+2)*LDK + gi] = E.z;
                        KT2[(jj-16+3)*LDK + gi] = E.w;
                    }
                }
                float* tsw = Asrc; Asrc = Adst; Adst = tsw;
                __syncthreads();
            }
        }
        // KT2[i][r] = Kg[i][r]

        // ---- P13: measurement update + filtered output ----
        {
            const size_t ob = ib * 2112;
            if (tid >= 480) {
                const int i = tid - 480;
                float4 s4 = make_float4(0.f,0.f,0.f,0.f);
                #pragma unroll
                for (int r0 = 0; r0 < 16; r0 += 4) {
                    float4 k4 = *(const float4*)(KT2 + i * LDK + r0);
                    float4 d4 = *(const float4*)(dz + r0);
                    FMA4L(s4, k4, d4);
                }
                float nm = zm[i] + (s4.x + s4.y) + (s4.z + s4.w);
                zm[i] = nm;
                out[ob + i] = nm;
                if (t == TLEN - 1) out[ob + 1056 + i] = nm;
            }
            if (tid < 256) {
                float4 acc = *(const float4*)(zc + i4 * LD + j4);
                #pragma unroll
                for (int r0 = 0; r0 < 16; r0 += 4) {
                    float4 k4 = *(const float4*)(KT2 + i4 * LDK + r0);
                    float4 m;
                    m = *(const float4*)(pCPm + (r0+0)*LD + j4); acc = f4fma(-k4.x, m, acc);
                    m = *(const float4*)(pCPm + (r0+1)*LD + j4); acc = f4fma(-k4.y, m, acc);
                    m = *(const float4*)(pCPm + (r0+2)*LD + j4); acc = f4fma(-k4.z, m, acc);
                    m = *(const float4*)(pCPm + (r0+3)*LD + j4); acc = f4fma(-k4.w, m, acc);
                }
                *(float4*)(zc + i4 * LD + j4) = acc;
                *(float4*)(out + ob + 32 + i4 * 32 + j4) = acc;
                if (t == TLEN - 1) *(float4*)(out + ob + 1088 + i4 * 32 + j4) = acc;
            }
        }
        // no trailing barrier: next P0 writes disjoint smem; P0-end barrier orders zm/zc
    }

    // =============== BACKWARD RTS SMOOTHER ===============
    {   // preload buffers for first backward iteration (t = TLEN-2)
        const size_t ibl = (size_t)b * TLEN + (TLEN - 1);
        const size_t ibp = (size_t)b * TLEN + (TLEN - 2);
        if (tid < 8)  alB[8  + tid] = g_alpha[ibl * 8  + tid];   // mb0 = 1
        if (tid < 32) suB[32 + tid] = g_u    [ibl * 32 + tid];
        if (tid < 32) fmS[tid]      = out[ibp * 2112 + tid];     // pb0 = 0
        if (tid < 256)
            *(float4*)(fcS + i4 * LD + j4) =
                *(const float4*)(out + ibp * 2112 + 32 + i4 * 32 + j4);
    }
    __syncthreads();

    #pragma unroll 1
    for (int t = TLEN - 2; t >= 0; --t) {
        const size_t ib = (size_t)b * TLEN + t;
        const size_t ob = ib * 2112;
        const int pb = t & 1;          // fm/fc parity
        const int mb = (t + 1) & 1;    // alpha/u parity
        const bool hasprev = (t > 0);
        float* fcSp = fcS + pb * (32 * LD);
        float* fmSp = fmS + pb * 32;

        float pfa = 0.f, pfu = 0.f, pfm = 0.f;
        float4 pfc = make_float4(0.f,0.f,0.f,0.f);
        if (tid < 8)  pfa = g_alpha[ib * 8  + tid];
        if (tid < 32) pfu = g_u    [ib * 32 + tid];
        if (hasprev) {
            const size_t obp = (ib - 1) * 2112;
            if (tid < 32) pfm = out[obp + tid];
            if (tid < 256)
                pfc = *(const float4*)(out + obp + 32 + i4 * 32 + j4);
        }

        // ---- P0: mixtures A, A^T, B(tmpM) for step t+1 (256 thr) ----
        if (tid < 256) {
            const float* al = alB + mb * 8;
            float4 aa = make_float4(0.f,0.f,0.f,0.f);
            float4 bb = make_float4(0.f,0.f,0.f,0.f);
            #pragma unroll
            for (int k = 0; k < 8; ++k) {
                const float w = al[k];
                float4 m = *(const float4*)(sAm + k * 1024 + i4 * 32 + j4);
                FMA4S(aa, w, m);
                m = *(const float4*)(sBm + k * 1024 + i4 * 32 + j4);
                FMA4S(bb, w, m);
            }
            *(float4*)(pA + i4 * LD + j4) = aa;
            pAtr[(j4+0)*LD + i4] = aa.x; pAtr[(j4+1)*LD + i4] = aa.y;
            pAtr[(j4+2)*LD + i4] = aa.z; pAtr[(j4+3)*LD + i4] = aa.w;
            *(float4*)(tmpM + i4 * LD + j4) = bb;
        }
        __syncthreads();

        // ---- P1: N = A fc -> aug0 cols 32..63 ; dz (warp 15) ----
        if (tid < 256) {
            float4 acc = mm4(pA + i4 * LD, fcSp, LD, j4);
            *(float4*)(aug0 + i4 * LDA + 32 + j4) = acc;
        } else if (tid >= 480) {
            const int i = tid - 480;
            const float* su = suB + mb * 32;
            float4 s4 = make_float4(0.f,0.f,0.f,0.f);
            #pragma unroll
            for (int k0 = 0; k0 < 32; k0 += 4) {
                float4 m4 = *(const float4*)(tmpM + i * LD + k0);
                float4 v4 = *(const float4*)(su + k0);
                FMA4L(s4, m4, v4);
                m4 = *(const float4*)(pA + i * LD + k0);
                v4 = *(const float4*)(fmSp + k0);
                FMA4L(s4, m4, v4);
            }
            dz[i] = zm[i] - ((s4.x + s4.y) + (s4.z + s4.w));
        }
        __syncthreads();

        // ---- P2: P_pred = N A^T + Q -> pPp and aug0 left; store prefetch ----
        if (tid < 256) {
            float4 acc = mm4(aug0 + i4 * LDA + 32, pAtr, LD, j4);
            int d = i4 - j4;
            if (d >= 0 && d < 4) ((float*)&acc)[d] += qd[i4];
            *(float4*)(pPp + i4 * LD + j4) = acc;
            *(float4*)(aug0 + i4 * LDA + j4) = acc;
        }
        if (tid < 8)  alB[pb * 8  + tid] = pfa;
        if (tid < 32) suB[pb * 32 + tid] = pfu;
        if (hasprev) {
            if (tid < 32) fmS[mb * 32 + tid] = pfm;
            if (tid < 256)
                *(float4*)(fcS + mb * (32 * LD) + i4 * LD + j4) = pfc;
        }
        __syncthreads();

        // ---- GJ bwd: 32 pivots, 4/phase, 16 col-groups x 32 rows (512 thr) ----
        {
            const int gi   = tid & 31;
            const int gcol = tid >> 5;      // 0..15
            const int jj   = gcol << 2;
            float* Asrc = aug0; float* Adst = aug1;
            #pragma unroll
            for (int pp = 0; pp < 8; ++pp) {
                if (pp < 7 || jj >= 32) {
                    GJ4 s = gj4_pre(Asrc, gi, pp << 2);
                    float4 E = gj4_col4(s, Asrc, jj);
                    *(float4*)(Adst + gi * LDA + jj) = E;
                    if (pp == 7) {
                        Ytr[(jj-32+0)*LD + gi] = E.x;
                        Ytr[(jj-32+1)*LD + gi] = E.y;
                        Ytr[(jj-32+2)*LD + gi] = E.z;
                        Ytr[(jj-32+3)*LD + gi] = E.w;
                    }
                }
                float* tsw = Asrc; Asrc = Adst; Adst = tsw;
                __syncthreads();
            }
        }
        // Y in aug0 cols 32..63 ; Ytr[i][k] = Y[k][i]

        // ---- PW: W = (Ps - Ppred) Y -> aug1 ; zs = fm + Ytr dz (warp 15) ----
        if (tid < 256) {
            float4 acc = mmdiff4(zc + i4 * LD, pPp + i4 * LD, aug0 + 32, LDA, j4);
            *(float4*)(aug1 + i4 * LDA + j4) = acc;
        } else if (tid >= 480) {
            const int i = tid - 480;
            float4 s4 = make_float4(0.f,0.f,0.f,0.f);
            #pragma unroll
            for (int k0 = 0; k0 < 32; k0 += 4) {
                float4 y4 = *(const float4*)(Ytr + i * LD + k0);
                float4 d4 = *(const float4*)(dz + k0);
                FMA4L(s4, y4, d4);
            }
            float nm = fmSp[i] + (s4.x + s4.y) + (s4.z + s4.w);
            zm[i] = nm;
            out[ob + 1056 + i] = nm;
        }
        __syncthreads();

        // ---- P21: Ps = fc + Ytr W -> zc, write sc ----
        if (tid < 256) {
            float4 w = mm4(Ytr + i4 * LD, aug1, LDA, j4);
            float4 acc = *(const float4*)(fcSp + i4 * LD + j4);
            acc.x += w.x; acc.y += w.y; acc.z += w.z; acc.w += w.w;
            *(float4*)(zc + i4 * LD + j4) = acc;
            *(float4*)(out + ob + 1088 + i4 * 32 + j4) = acc;
        }
        // no trailing barrier: next P0 writes pA/pAtr/tmpM (not read here);
        // aug1/Ytr rewritten only after multiple barriers next iteration.
    }
}

extern "C" void kernel_launch(void* const* d_in, const int* in_sizes, int n_in,
                              void* d_out, int out_size) {
    const float* g_a    = (const float*)d_in[0];
    const float* g_alpha= (const float*)d_in[1];
    const float* g_u    = (const float*)d_in[2];
    const float* g_A    = (const float*)d_in[3];
    const float* g_B    = (const float*)d_in[4];
    const float* g_C    = (const float*)d_in[5];
    const float* g_lQ   = (const float*)d_in[6];
    const float* g_lR   = (const float*)d_in[7];
    const float* g_z0m  = (const float*)d_in[8];
    const float* g_z0lv = (const float*)d_in[9];
    float* out = (float*)d_out;
    int B = in_sizes[0] / (TLEN * 16);
    size_t smem = SMEM_FLOATS * sizeof(float);
    cudaFuncSetAttribute(lgssm_kernel, cudaFuncAttributeMaxDynamicSharedMemorySize, (int)smem);
    lgssm_kernel<<<B, NT, smem>>>(g_a, g_alpha, g_u, g_A, g_B, g_C,
                                  g_lQ, g_lR, g_z0m, g_z0lv, out);
}

// round 9
// speedup vs baseline: 2.2824x; 1.2978x over previous
#include <cuda_runtime.h>

#define NT     512
#define TLEN   512
#define LD     36     // padded leading dim, 32-col matrices
#define LDA    68     // Y-augmented GJ matrix leading dim (32x64)
#define LDS2   52     // S-augmented GJ matrix leading dim (16x48)
#define LDCT   20     // C-transpose leading dim
#define LDK    20     // KT2 leading dim
#define MAXB   128

// scratch: smoother gains & predicted stats produced in forward pass
__device__ float g_Y [MAXB * TLEN * 1024];
__device__ float g_Nm[MAXB * TLEN * 1024];
__device__ float g_zp[MAXB * TLEN * 32];

// ---- shared memory layout (float offsets) ----
#define O_SAM  0       // 8*32*32 A components
#define O_SBM  8192
#define O_SCM  16384   // 8*16*32 C components
#define O_A    20480   // 32xLD
#define O_ATR  21632   // 32xLD
#define O_CM   22784   // 16xLD
#define O_CTR  23360   // 32xLDCT
#define O_ZC   24000   // 32xLD covariance state (filtered / Ps)
#define O_TMP  25152   // 32xLD B mixture
#define O_PP   26304   // 32xLD Ppred
#define O_CPM  27456   // 16xLD M = C*Ppred
#define O_AUG0 28032   // 32xLDA Y-GJ buffer 0
#define O_AUG1 30208   // 32xLDA Y-GJ buffer 1 (bwd: W)
#define O_AGS0 32384   // 16xLDS2 S-GJ buffer 0
#define O_AGS1 33216   // 16xLDS2 S-GJ buffer 1
#define O_KT2  34048   // 32xLDK  Kg (row i, col r)
#define O_FCS  34688   // 2 x 1152 filtered cov (parity)
#define O_FMS  36992   // 2 x 32
#define O_YB   37056   // 2 x 1152  Y (parity)
#define O_YT   39360   // 2 x 1152  Y^T (parity)
#define O_NB   41664   // 2 x 1152  N (parity)
#define O_ZPS  43968   // 2 x 32    zpred (parity)
#define O_ZM   44032   // 32
#define O_ZM2  44064   // 32
#define O_AL   44096   // 2 x 8
#define O_SU   44112   // 2 x 32
#define O_SA   44176   // 2 x 16
#define O_AP   44208   // 16
#define O_DZ   44224   // 32
#define O_QD   44256   // 32
#define O_RD   44288   // 16
#define SMEM_FLOATS 44304

__device__ __forceinline__ float4 f4fma(float s, float4 b, float4 a) {  // a + s*b
    return make_float4(fmaf(s,b.x,a.x), fmaf(s,b.y,a.y), fmaf(s,b.z,a.z), fmaf(s,b.w,a.w));
}
__device__ __forceinline__ float4 f4scale(float4 a, float s) {
    return make_float4(a.x*s, a.y*s, a.z*s, a.w*s);
}
#define FMA4S(acc, s, b)                                                      \
    acc.x = fmaf((s), (b).x, acc.x); acc.y = fmaf((s), (b).y, acc.y);         \
    acc.z = fmaf((s), (b).z, acc.z); acc.w = fmaf((s), (b).w, acc.w);
#define FMA4L(s4, m4, v4)                                                     \
    s4.x = fmaf(m4.x, v4.x, s4.x); s4.y = fmaf(m4.y, v4.y, s4.y);             \
    s4.z = fmaf(m4.z, v4.z, s4.z); s4.w = fmaf(m4.w, v4.w, s4.w);

// C[i][j..j+3] = rowA[0..31] . matB[0..31][j..j+3]
__device__ __forceinline__ float4 mm4(const float* __restrict__ rowA,
                                      const float* __restrict__ matB,
                                      const int ldB, const int jj) {
    float4 a0 = make_float4(0.f,0.f,0.f,0.f);
    float4 a1 = make_float4(0.f,0.f,0.f,0.f);
    #pragma unroll
    for (int k0 = 0; k0 < 32; k0 += 8) {
        float4 x = *(const float4*)(rowA + k0);
        float4 y = *(const float4*)(rowA + k0 + 4);
        const float* Bp = matB + k0 * ldB + jj;
        float4 b;
        b = *(const float4*)(Bp);           FMA4S(a0, x.x, b);
        b = *(const float4*)(Bp + ldB);     FMA4S(a1, x.y, b);
        b = *(const float4*)(Bp + 2*ldB);   FMA4S(a0, x.z, b);
        b = *(const float4*)(Bp + 3*ldB);   FMA4S(a1, x.w, b);
        b = *(const float4*)(Bp + 4*ldB);   FMA4S(a0, y.x, b);
        b = *(const float4*)(Bp + 5*ldB);   FMA4S(a1, y.y, b);
        b = *(const float4*)(Bp + 6*ldB);   FMA4S(a0, y.z, b);
        b = *(const float4*)(Bp + 7*ldB);   FMA4S(a1, y.w, b);
    }
    return make_float4(a0.x + a1.x, a0.y + a1.y, a0.z + a1.z, a0.w + a1.w);
}

// ---- 4-pivot Gauss-Jordan block state ----
struct GJ4 {
    float inv0, inv1, inv2, inv3;
    float P10, P20, P30, a21, a31, a32;
    float c0, c1, c2, c3;
    int p0, gi;
};
__device__ __forceinline__ GJ4 gj4_pre(const float* __restrict__ Asrc, int gi,
                                       int p0, int lda) {
    GJ4 s; s.p0 = p0; s.gi = gi;
    const float4 R0 = *(const float4*)(Asrc + (p0+0)*lda + p0);
    const float4 R1 = *(const float4*)(Asrc + (p0+1)*lda + p0);
    const float4 R2 = *(const float4*)(Asrc + (p0+2)*lda + p0);
    const float4 R3 = *(const float4*)(Asrc + (p0+3)*lda + p0);
    const float4 Ci = *(const float4*)(Asrc + gi*lda + p0);
    s.inv0 = __fdividef(1.f, R0.x);
    float u01 = R0.y*s.inv0, u02 = R0.z*s.inv0, u03 = R0.w*s.inv0;
    s.P10 = R1.x;
    float a11 = fmaf(-R1.x, u01, R1.y);  s.inv1 = __fdividef(1.f, a11);
    float a12 = fmaf(-R1.x, u02, R1.z), a13 = fmaf(-R1.x, u03, R1.w);
    float v12 = a12*s.inv1, v13 = a13*s.inv1;
    s.P20 = R2.x;
    s.a21 = fmaf(-R2.x, u01, R2.y);
    float a22 = fmaf(-s.a21, v12, fmaf(-R2.x, u02, R2.z));
    s.inv2 = __fdividef(1.f, a22);
    float a23 = fmaf(-s.a21, v13, fmaf(-R2.x, u03, R2.w));
    float w23 = a23*s.inv2;
    s.P30 = R3.x;
    s.a31 = fmaf(-R3.x, u01, R3.y);
    s.a32 = fmaf(-s.a31, v12, fmaf(-R3.x, u02, R3.z));
    float a33 = fmaf(-s.a32, w23, fmaf(-s.a31, v13, fmaf(-R3.x, u03, R3.w)));
    s.inv3 = __fdividef(1.f, a33);
    s.c0 = Ci.x;
    s.c1 = (gi==p0)   ? u01 : fmaf(-s.c0, u01, Ci.y);
    float c2t = (gi==p0)   ? u02 : fmaf(-s.c0, u02, Ci.z);
    s.c2 = (gi==p0+1) ? v12 : fmaf(-s.c1, v12, c2t);
    float c3t = (gi==p0)   ? u03 : fmaf(-s.c0, u03, Ci.w);
    float c3u = (gi==p0+1) ? v13 : fmaf(-s.c1, v13, c3t);
    s.c3 = (gi==p0+2) ? w23 : fmaf(-s.c2, w23, c3u);
    return s;
}
__device__ __forceinline__ float4 gj4_col4(const GJ4& s, const float* __restrict__ Asrc,
                                           int jj, int lda) {
    const int p0 = s.p0, gi = s.gi;
    float4 m0 = *(const float4*)(Asrc + (p0+0)*lda + jj);
    float4 m1 = *(const float4*)(Asrc + (p0+1)*lda + jj);
    float4 m2 = *(const float4*)(Asrc + (p0+2)*lda + jj);
    float4 m3 = *(const float4*)(Asrc + (p0+3)*lda + jj);
    float4 mi = *(const float4*)(Asrc + gi*lda + jj);
    float4 r0 = f4scale(m0, s.inv0);
    float4 E  = (gi==p0)   ? r0 : f4fma(-s.c0, r0, mi);
    float4 t1 = f4fma(-s.P10, r0, m1);
    float4 r1 = f4scale(t1, s.inv1);
    E = (gi==p0+1) ? r1 : f4fma(-s.c1, r1, E);
    float4 t2 = f4fma(-s.a21, r1, f4fma(-s.P20, r0, m2));
    float4 r2 = f4scale(t2, s.inv2);
    E = (gi==p0+2) ? r2 : f4fma(-s.c2, r2, E);
    float4 t3 = f4fma(-s.a32, r2, f4fma(-s.a31, r1, f4fma(-s.P30, r0, m3)));
    float4 r3 = f4scale(t3, s.inv3);
    E = (gi==p0+3) ? r3 : f4fma(-s.c3, r3, E);
    return E;
}

__global__ __launch_bounds__(NT, 1)
void lgssm_kernel(const float* __restrict__ g_a,   const float* __restrict__ g_alpha,
                  const float* __restrict__ g_u,   const float* __restrict__ g_A,
                  const float* __restrict__ g_B,   const float* __restrict__ g_C,
                  const float* __restrict__ g_lQ,  const float* __restrict__ g_lR,
                  const float* __restrict__ g_z0m, const float* __restrict__ g_z0lv,
                  float* __restrict__ out)
{
    extern __shared__ float sh[];
    float* sAm  = sh + O_SAM;
    float* sBm  = sh + O_SBM;
    float* sCm  = sh + O_SCM;
    float* pA   = sh + O_A;
    float* pAtr = sh + O_ATR;
    float* pCm  = sh + O_CM;
    float* pCtr = sh + O_CTR;
    float* zc   = sh + O_ZC;
    float* tmpM = sh + O_TMP;
    float* pPp  = sh + O_PP;
    float* pCPm = sh + O_CPM;
    float* aug0 = sh + O_AUG0;
    float* aug1 = sh + O_AUG1;
    float* augS0= sh + O_AGS0;
    float* augS1= sh + O_AGS1;
    float* KT2  = sh + O_KT2;
    float* fcS  = sh + O_FCS;
    float* fmS  = sh + O_FMS;
    float* Ybuf = sh + O_YB;
    float* YtrB = sh + O_YT;
    float* NbS  = sh + O_NB;
    float* zpS  = sh + O_ZPS;
    float* zm   = sh + O_ZM;
    float* zm2  = sh + O_ZM2;
    float* alB  = sh + O_AL;
    float* suB  = sh + O_SU;
    float* saB  = sh + O_SA;
    float* apred= sh + O_AP;
    float* dz   = sh + O_DZ;
    float* qd   = sh + O_QD;
    float* rd   = sh + O_RD;

    const int tid = threadIdx.x;
    const int b   = blockIdx.x;
    const int i4  = tid >> 3;          // 0..31 for tid<256
    const int j4  = (tid & 7) << 2;    // 0,4..28

    // ---- preload constants, noise diagonals, t=0 inputs, init state ----
    for (int idx = tid; idx < 8192; idx += NT) sAm[idx] = g_A[idx];
    for (int idx = tid; idx < 8192; idx += NT) sBm[idx] = g_B[idx];
    for (int idx = tid; idx < 4096; idx += NT) sCm[idx] = g_C[idx];
    if (tid < 32) qd[tid] = expf(g_lQ[tid]);
    if (tid < 16) rd[tid] = expf(g_lR[tid]);
    {
        const size_t ib0 = (size_t)b * TLEN;
        if (tid < 8)  alB[tid] = g_alpha[ib0 * 8  + tid];
        if (tid < 32) suB[tid] = g_u    [ib0 * 32 + tid];
        if (tid < 16) saB[tid] = g_a    [ib0 * 16 + tid];
        if (tid < 32) { zm[tid] = g_z0m[tid]; zm2[tid] = g_z0m[tid]; }
        if (tid < 256) {
            float4 v = make_float4(0.f, 0.f, 0.f, 0.f);
            int d = i4 - j4;
            if (d >= 0 && d < 4) ((float*)&v)[d] = expf(g_z0lv[i4]);
            *(float4*)(pPp + i4 * LD + j4) = v;   // "Ppred" at t=0 = prior cov
        }
    }
    __syncthreads();

    // =============== FORWARD FILTER (also produces Y, N, zpred for smoother) ===
    #pragma unroll 1
    for (int t = 0; t < TLEN; ++t) {
        const size_t ib = (size_t)b * TLEN + t;
        const int pb = t & 1, nb = pb ^ 1;
        const bool hasnext = (t + 1 < TLEN);

        float pfa = 0.f, pfu = 0.f, pfo = 0.f;
        if (hasnext) {
            if (tid < 8)  pfa = g_alpha[(ib + 1) * 8  + tid];
            if (tid < 32) pfu = g_u    [(ib + 1) * 32 + tid];
            if (tid < 16) pfo = g_a    [(ib + 1) * 16 + tid];
        }

        // ---- P0: mixtures A, A^T, B(tmpM), C, C^T ----
        if (tid < 256) {
            const float* al = alB + pb * 8;
            float4 aa = make_float4(0.f,0.f,0.f,0.f);
            float4 bb = make_float4(0.f,0.f,0.f,0.f);
            #pragma unroll
            for (int k = 0; k < 8; ++k) {
                const float w = al[k];
                float4 m = *(const float4*)(sAm + k * 1024 + i4 * 32 + j4);
                FMA4S(aa, w, m);
                m = *(const float4*)(sBm + k * 1024 + i4 * 32 + j4);
                FMA4S(bb, w, m);
            }
            *(float4*)(pA + i4 * LD + j4) = aa;
            pAtr[(j4+0)*LD + i4] = aa.x; pAtr[(j4+1)*LD + i4] = aa.y;
            pAtr[(j4+2)*LD + i4] = aa.z; pAtr[(j4+3)*LD + i4] = aa.w;
            *(float4*)(tmpM + i4 * LD + j4) = bb;
        } else {
            const int ii = i4 - 32;
            if (ii < 16) {
                const float* al = alB + pb * 8;
                float4 cc = make_float4(0.f,0.f,0.f,0.f);
                #pragma unroll
                for (int k = 0; k < 8; ++k) {
                    const float w = al[k];
                    float4 m = *(const float4*)(sCm + k * 512 + ii * 32 + j4);
                    FMA4S(cc, w, m);
                }
                *(float4*)(pCm + ii * LD + j4) = cc;
                pCtr[(j4+0)*LDCT + ii] = cc.x; pCtr[(j4+1)*LDCT + ii] = cc.y;
                pCtr[(j4+2)*LDCT + ii] = cc.z; pCtr[(j4+3)*LDCT + ii] = cc.w;
            }
        }
        __syncthreads();

        if (t > 0) {
            // ---- P1: N = A zc -> aug0 cols 32..63 ; zm2 = A zm + B u (warp 15)
            if (tid < 256) {
                float4 acc = mm4(pA + i4 * LD, zc, LD, j4);
                *(float4*)(aug0 + i4 * LDA + 32 + j4) = acc;
            } else if (tid >= 480) {
                const int i = tid - 480;
                const float* su = suB + pb * 32;
                float4 s4 = make_float4(0.f,0.f,0.f,0.f);
                #pragma unroll
                for (int k0 = 0; k0 < 32; k0 += 4) {
                    float4 m4 = *(const float4*)(tmpM + i * LD + k0);
                    float4 v4 = *(const float4*)(su + k0);
                    FMA4L(s4, m4, v4);
                    m4 = *(const float4*)(pA + i * LD + k0);
                    v4 = *(const float4*)(zm + k0);
                    FMA4L(s4, m4, v4);
                }
                zm2[i] = (s4.x + s4.y) + (s4.z + s4.w);
            }
            __syncthreads();
            // ---- P2: Ppred = N A^T + Q -> pPp + aug0 cols 0..31 ; STG zpred --
            if (tid < 256) {
                float4 acc = mm4(aug0 + i4 * LDA + 32, pAtr, LD, j4);
                int d = i4 - j4;
                if (d >= 0 && d < 4) ((float*)&acc)[d] += qd[i4];
                *(float4*)(pPp + i4 * LD + j4) = acc;
                *(float4*)(aug0 + i4 * LDA + j4) = acc;
            } else if (tid >= 448 && tid < 480) {
                g_zp[(ib - 1) * 32 + (tid - 448)] = zm2[tid - 448];
            }
            __syncthreads();
        }

        // ---- P3: M = C Ppred -> pCPm + augS cols 16..47 ; STG N ; apred ----
        if (tid < 128) {
            const int i = tid >> 3;   // 0..15
            float4 acc = mm4(pCm + i * LD, pPp, LD, j4);
            *(float4*)(pCPm + i * LD + j4) = acc;
            *(float4*)(augS0 + i * LDS2 + 16 + j4) = acc;
        }
        if (t > 0 && tid < 256) {
            *(float4*)(g_Nm + (ib - 1) * 1024 + i4 * 32 + j4) =
                *(const float4*)(aug0 + i4 * LDA + 32 + j4);
        }
        if (tid >= 480 && tid < 496) {
            const int i = tid - 480;
            float4 s4 = make_float4(0.f,0.f,0.f,0.f);
            #pragma unroll
            for (int k0 = 0; k0 < 32; k0 += 4) {
                float4 m4 = *(const float4*)(pCm + i * LD + k0);
                float4 v4 = *(const float4*)(zm2 + k0);
                FMA4L(s4, m4, v4);
            }
            apred[i] = (s4.x + s4.y) + (s4.z + s4.w);
        }
        __syncthreads();

        // ---- P4: S -> augS cols 0..15 ; dz ; store prefetched inputs ----
        if (tid < 64) {
            const int i = tid >> 2, j0 = (tid & 3) << 2;
            float4 acc = mm4(pCPm + i * LD, pCtr, LDCT, j0);
            int d = i - j0;
            if (d >= 0 && d < 4) ((float*)&acc)[d] += rd[i];
            *(float4*)(augS0 + i * LDS2 + j0) = acc;
        } else if (tid >= 128 && tid < 144) {
            const int j = tid - 128;
            dz[j] = saB[pb * 16 + j] - apred[j];
        }
        if (hasnext) {
            if (tid < 8)  alB[nb * 8  + tid] = pfa;
            if (tid < 32) suB[nb * 32 + tid] = pfu;
            if (tid < 16) saB[nb * 16 + tid] = pfo;
        }
        __syncthreads();

        // ---- combined GJ: Y-solve (32 piv, 8 phases, 256 thr) +
        //                   S-solve (16 piv, phases 0-3, thr 256..447) ----
        {
            float* Ys = aug0; float* Yd = aug1;
            float* Ss = augS0; float* Sd = augS1;
            const int yi  = tid >> 3;
            const int yjA = (tid & 7) << 2;
            const int yjB = yjA + 32;
            const int sidx = tid - 256;
            const int si = sidx & 15;
            const int sg = sidx >> 4;
            const int sj = sg << 2;
            #pragma unroll
            for (int pp = 0; pp < 8; ++pp) {
                if (tid < 256) {
                    if (t > 0) {
                        GJ4 s = gj4_pre(Ys, yi, pp << 2, LDA);
                        float4 EA = gj4_col4(s, Ys, yjA, LDA);
                        float4 EB = gj4_col4(s, Ys, yjB, LDA);
                        *(float4*)(Yd + yi * LDA + yjA) = EA;
                        *(float4*)(Yd + yi * LDA + yjB) = EB;
                    }
                } else if (sidx < 192 && pp < 4) {
                    if (pp < 3 || sj >= 16) {
                        GJ4 s = gj4_pre(Ss, si, pp << 2, LDS2);
                        float4 E = gj4_col4(s, Ss, sj, LDS2);
                        if (pp < 3) {
                            *(float4*)(Sd + si * LDS2 + sj) = E;
                        } else {
                            KT2[(sj-16+0)*LDK + si] = E.x;
                            KT2[(sj-16+1)*LDK + si] = E.y;
                            KT2[(sj-16+2)*LDK + si] = E.z;
                            KT2[(sj-16+3)*LDK + si] = E.w;
                        }
                    }
                }
                float* w;
                w = Ys; Ys = Yd; Yd = w;
                w = Ss; Ss = Sd; Sd = w;
                __syncthreads();
            }
        }
        // Y = Ppred^-1 N in aug0 cols 32..63 ; KT2[i][r] = Kg[i][r]

        // ---- P13: measurement update, outputs, STG Y ----
        {
            const size_t ob = ib * 2112;
            if (tid < 256) {
                float4 acc = *(const float4*)(pPp + i4 * LD + j4);
                #pragma unroll
                for (int r0 = 0; r0 < 16; r0 += 4) {
                    float4 k4 = *(const float4*)(KT2 + i4 * LDK + r0);
                    float4 m;
                    m = *(const float4*)(pCPm + (r0+0)*LD + j4); acc = f4fma(-k4.x, m, acc);
                    m = *(const float4*)(pCPm + (r0+1)*LD + j4); acc = f4fma(-k4.y, m, acc);
                    m = *(const float4*)(pCPm + (r0+2)*LD + j4); acc = f4fma(-k4.z, m, acc);
                    m = *(const float4*)(pCPm + (r0+3)*LD + j4); acc = f4fma(-k4.w, m, acc);
                }
                *(float4*)(zc + i4 * LD + j4) = acc;
                *(float4*)(out + ob + 32 + i4 * 32 + j4) = acc;
                if (t == TLEN - 1) *(float4*)(out + ob + 1088 + i4 * 32 + j4) = acc;
                if (t > 0)
                    *(float4*)(g_Y + (ib - 1) * 1024 + i4 * 32 + j4) =
                        *(const float4*)(aug0 + i4 * LDA + 32 + j4);
            } else if (tid >= 480) {
                const int i = tid - 480;
                float4 s4 = make_float4(0.f,0.f,0.f,0.f);
                #pragma unroll
                for (int r0 = 0; r0 < 16; r0 += 4) {
                    float4 k4 = *(const float4*)(KT2 + i * LDK + r0);
                    float4 d4 = *(const float4*)(dz + r0);
                    FMA4L(s4, k4, d4);
                }
                float nm = zm2[i] + (s4.x + s4.y) + (s4.z + s4.w);
                zm[i] = nm;
                out[ob + i] = nm;
                if (t == TLEN - 1) out[ob + 1056 + i] = nm;
            }
        }
        // no trailing barrier: next P0 writes disjoint smem; P0-end barrier orders
    }

    // =============== BACKWARD RTS SMOOTHER (2 phases/step) ===============
    __syncthreads();
    {   // preload slot TLEN-2 into parity 0
        const size_t slot0 = (size_t)b * TLEN + (TLEN - 2);
        if (tid < 256) {
            float4 y = *(const float4*)(g_Y  + slot0 * 1024 + i4 * 32 + j4);
            float4 n = *(const float4*)(g_Nm + slot0 * 1024 + i4 * 32 + j4);
            *(float4*)(Ybuf + i4 * LD + j4) = y;
            YtrB[(j4+0)*LD + i4] = y.x; YtrB[(j4+1)*LD + i4] = y.y;
            YtrB[(j4+2)*LD + i4] = y.z; YtrB[(j4+3)*LD + i4] = y.w;
            *(float4*)(NbS + i4 * LD + j4) = n;
            *(float4*)(fcS + i4 * LD + j4) =
                *(const float4*)(out + slot0 * 2112 + 32 + i4 * 32 + j4);
        }
        if (tid < 32) {
            zpS[tid] = g_zp[slot0 * 32 + tid];
            fmS[tid] = out[slot0 * 2112 + tid];
        }
    }
    __syncthreads();

    #pragma unroll 1
    for (int t = TLEN - 2; t >= 0; --t) {
        const size_t ib = (size_t)b * TLEN + t;
        const size_t ob = ib * 2112;
        const int pb = t & 1;
        const int nb = pb ^ 1;
        const bool hasprev = (t > 0);

        // prefetch slot t-1
        float4 pfY = make_float4(0.f,0.f,0.f,0.f);
        float4 pfN = make_float4(0.f,0.f,0.f,0.f);
        float4 pfc = make_float4(0.f,0.f,0.f,0.f);
        float pfz = 0.f, pfm = 0.f;
        if (hasprev) {
            const size_t sp = ib - 1;
            if (tid < 256) {
                pfY = *(const float4*)(g_Y  + sp * 1024 + i4 * 32 + j4);
                pfN = *(const float4*)(g_Nm + sp * 1024 + i4 * 32 + j4);
                pfc = *(const float4*)(out + sp * 2112 + 32 + i4 * 32 + j4);
            } else if (tid >= 448 && tid < 480) {
                pfz = g_zp[sp * 32 + (tid - 448)];
                pfm = out[sp * 2112 + (tid - 448)];
            }
        }

        // ---- PW: W = Ps*Y - N -> aug1 ; zs2 = fm + Ytr(zs - zpred) (warp 15)
        if (tid < 256) {
            float4 acc = mm4(zc + i4 * LD, Ybuf + pb * 1152, LD, j4);
            float4 n4 = *(const float4*)(NbS + pb * 1152 + i4 * LD + j4);
            acc.x -= n4.x; acc.y -= n4.y; acc.z -= n4.z; acc.w -= n4.w;
            *(float4*)(aug1 + i4 * LDA + j4) = acc;
        } else if (tid >= 480) {
            const int i = tid - 480;
            float4 s4 = make_float4(0.f,0.f,0.f,0.f);
            #pragma unroll
            for (int k0 = 0; k0 < 32; k0 += 4) {
                float4 y4 = *(const float4*)(YtrB + pb * 1152 + i * LD + k0);
                float4 z4 = *(const float4*)(zm + k0);
                float4 p4 = *(const float4*)(zpS + pb * 32 + k0);
                float4 d4 = make_float4(z4.x-p4.x, z4.y-p4.y, z4.z-p4.z, z4.w-p4.w);
                FMA4L(s4, y4, d4);
            }
            zm2[i] = fmS[pb * 32 + i] + (s4.x + s4.y) + (s4.z + s4.w);
        }
        __syncthreads();

        // ---- P21: Ps = fc + Ytr W -> zc + out ; zs out ; store prefetch [nb] -
        if (tid < 256) {
            float4 w = mm4(YtrB + pb * 1152 + i4 * LD, aug1, LDA, j4);
            float4 acc = *(const float4*)(fcS + pb * 1152 + i4 * LD + j4);
            acc.x += w.x; acc.y += w.y; acc.z += w.z; acc.w += w.w;
            *(float4*)(zc + i4 * LD + j4) = acc;
            *(float4*)(out + ob + 1088 + i4 * 32 + j4) = acc;
            if (hasprev) {
                *(float4*)(Ybuf + nb * 1152 + i4 * LD + j4) = pfY;
                YtrB[nb * 1152 + (j4+0)*LD + i4] = pfY.x;
                YtrB[nb * 1152 + (j4+1)*LD + i4] = pfY.y;
                YtrB[nb * 1152 + (j4+2)*LD + i4] = pfY.z;
                YtrB[nb * 1152 + (j4+3)*LD + i4] = pfY.w;
                *(float4*)(NbS + nb * 1152 + i4 * LD + j4) = pfN;
                *(float4*)(fcS + nb * 1152 + i4 * LD + j4) = pfc;
            }
        } else if (tid >= 448 && tid < 480) {
            const int i = tid - 448;
            float nm = zm2[i];
            zm[i] = nm;
            out[ob + 1056 + i] = nm;
            if (hasprev) {
                zpS[nb * 32 + i] = pfz;
                fmS[nb * 32 + i] = pfm;
            }
        }
        __syncthreads();
    }
}

extern "C" void kernel_launch(void* const* d_in, const int* in_sizes, int n_in,
                              void* d_out, int out_size) {
    const float* g_a    = (const float*)d_in[0];
    const float* g_alpha= (const float*)d_in[1];
    const float* g_u    = (const float*)d_in[2];
    const float* g_A    = (const float*)d_in[3];
    const float* g_B    = (const float*)d_in[4];
    const float* g_C    = (const float*)d_in[5];
    const float* g_lQ   = (const float*)d_in[6];
    const float* g_lR   = (const float*)d_in[7];
    const float* g_z0m  = (const float*)d_in[8];
    const float* g_z0lv = (const float*)d_in[9];
    float* out = (float*)d_out;
    int B = in_sizes[0] / (TLEN * 16);
    size_t smem = SMEM_FLOATS * sizeof(float);
    cudaFuncSetAttribute(lgssm_kernel, cudaFuncAttributeMaxDynamicSharedMemorySize, (int)smem);
    lgssm_kernel<<<B, NT, smem>>>(g_a, g_alpha, g_u, g_A, g_B, g_C,
                                  g_lQ, g_lR, g_z0m, g_z0lv, out);
}

// round 10
// speedup vs baseline: 2.2825x; 1.0000x over previous
#include <cuda_runtime.h>

#define NT     512
#define TLEN   512
#define LD     36     // padded leading dim, 32-col matrices
#define LDA    68     // Y-augmented GJ matrix leading dim (32x64)
#define LDS2   52     // S-augmented GJ matrix leading dim (16x48)
#define LDCT   20     // C^T / CA^T / CQC leading dim
#define LDK    20     // KT2 leading dim
#define MAXB   128

// scratch: smoother gains & predicted stats produced in forward pass
__device__ float g_Y [MAXB * TLEN * 1024];
__device__ float g_Nm[MAXB * TLEN * 1024];
__device__ float g_zp[MAXB * TLEN * 32];

// ---- shared memory layout (float offsets) ----
#define O_SAM  0
#define O_SBM  8192
#define O_SCM  16384
#define O_A    20480   // 32xLD A_t
#define O_ATR  21632   // 32xLD A_t^T
#define O_CM   22784   // 16xLD C_t
#define O_CTR  23360   // 32xLDCT C_t^T
#define O_ZC   24000   // 32xLD covariance state (filtered / Ps)
#define O_TMP  25152   // 32xLD B mixture (P2+: CN in rows 0-15)
#define O_PP   26304   // 32xLD Ppred
#define O_CPM  27456   // 16xLD M = C*Ppred
#define O_AUG0 28032   // 32xLDA Y-GJ buffer 0
#define O_AUG1 30208   // 32xLDA Y-GJ buffer 1 (bwd: W)
#define O_AGS0 32384   // 16xLDS2 S-GJ buffer 0
#define O_AGS1 33216   // 16xLDS2 S-GJ buffer 1
#define O_KT2  34048   // 32xLDK Kg (row i, col r)
#define O_FCS  34688   // 2 x 1152 filtered cov (parity)
#define O_FMS  36992   // 2 x 32
#define O_YB   37056   // 2 x 1152 Y (parity)
#define O_YT   39360   // 2 x 1152 Y^T (parity)
#define O_NB   41664   // 2 x 1152 N (parity)
#define O_ZPS  43968   // 2 x 32 zpred (parity)
#define O_ZM   44032   // 32
#define O_ZM2  44064   // 32
#define O_AL   44096   // 2 x 8
#define O_SU   44112   // 2 x 32
#define O_SA   44176   // 2 x 16
#define O_AP   44208   // 16
#define O_DZ   44224   // 32
#define O_QD   44256   // 32
#define O_RD   44288   // 16
#define O_CAT  44304   // 32xLDCT  CA^T (CA = C*A)
#define O_CQC  44944   // 16xLDCT  C diag(q) C^T
#define SMEM_FLOATS 45264

__device__ __forceinline__ float4 f4fma(float s, float4 b, float4 a) {  // a + s*b
    return make_float4(fmaf(s,b.x,a.x), fmaf(s,b.y,a.y), fmaf(s,b.z,a.z), fmaf(s,b.w,a.w));
}
__device__ __forceinline__ float4 f4scale(float4 a, float s) {
    return make_float4(a.x*s, a.y*s, a.z*s, a.w*s);
}
#define FMA4S(acc, s, b)                                                      \
    acc.x = fmaf((s), (b).x, acc.x); acc.y = fmaf((s), (b).y, acc.y);         \
    acc.z = fmaf((s), (b).z, acc.z); acc.w = fmaf((s), (b).w, acc.w);
#define FMA4L(s4, m4, v4)                                                     \
    s4.x = fmaf(m4.x, v4.x, s4.x); s4.y = fmaf(m4.y, v4.y, s4.y);             \
    s4.z = fmaf(m4.z, v4.z, s4.z); s4.w = fmaf(m4.w, v4.w, s4.w);

// C[i][j..j+3] = rowA . matB[:, j..j+3]
__device__ __forceinline__ float4 mm4(const float* __restrict__ rowA,
                                      const float* __restrict__ matB,
                                      const int ldB, const int jj) {
    float4 a0 = make_float4(0.f,0.f,0.f,0.f);
    float4 a1 = make_float4(0.f,0.f,0.f,0.f);
    #pragma unroll
    for (int k0 = 0; k0 < 32; k0 += 8) {
        float4 x = *(const float4*)(rowA + k0);
        float4 y = *(const float4*)(rowA + k0 + 4);
        const float* Bp = matB + k0 * ldB + jj;
        float4 b;
        b = *(const float4*)(Bp);           FMA4S(a0, x.x, b);
        b = *(const float4*)(Bp + ldB);     FMA4S(a1, x.y, b);
        b = *(const float4*)(Bp + 2*ldB);   FMA4S(a0, x.z, b);
        b = *(const float4*)(Bp + 3*ldB);   FMA4S(a1, x.w, b);
        b = *(const float4*)(Bp + 4*ldB);   FMA4S(a0, y.x, b);
        b = *(const float4*)(Bp + 5*ldB);   FMA4S(a1, y.y, b);
        b = *(const float4*)(Bp + 6*ldB);   FMA4S(a0, y.z, b);
        b = *(const float4*)(Bp + 7*ldB);   FMA4S(a1, y.w, b);
    }
    return make_float4(a0.x + a1.x, a0.y + a1.y, a0.z + a1.z, a0.w + a1.w);
}

// two rows (rA0, rA1) x 4 cols: B loads shared between the rows
__device__ __forceinline__ void mm24(const float* __restrict__ rA0,
                                     const float* __restrict__ rA1,
                                     const float* __restrict__ matB,
                                     const int ldB, const int jj,
                                     float4& o0, float4& o1) {
    float4 a0 = make_float4(0.f,0.f,0.f,0.f);
    float4 a1 = make_float4(0.f,0.f,0.f,0.f);
    float4 c0 = make_float4(0.f,0.f,0.f,0.f);
    float4 c1 = make_float4(0.f,0.f,0.f,0.f);
    #pragma unroll
    for (int k0 = 0; k0 < 32; k0 += 4) {
        float4 x = *(const float4*)(rA0 + k0);
        float4 y = *(const float4*)(rA1 + k0);
        const float* Bp = matB + k0 * ldB + jj;
        float4 b;
        b = *(const float4*)(Bp);         FMA4S(a0, x.x, b); FMA4S(c0, y.x, b);
        b = *(const float4*)(Bp + ldB);   FMA4S(a1, x.y, b); FMA4S(c1, y.y, b);
        b = *(const float4*)(Bp + 2*ldB); FMA4S(a0, x.z, b); FMA4S(c0, y.z, b);
        b = *(const float4*)(Bp + 3*ldB); FMA4S(a1, x.w, b); FMA4S(c1, y.w, b);
    }
    o0 = make_float4(a0.x+a1.x, a0.y+a1.y, a0.z+a1.z, a0.w+a1.w);
    o1 = make_float4(c0.x+c1.x, c0.y+c1.y, c0.z+c1.z, c0.w+c1.w);
}

// ---- 4-pivot Gauss-Jordan block state ----
struct GJ4 {
    float inv0, inv1, inv2, inv3;
    float P10, P20, P30, a21, a31, a32;
    float c0, c1, c2, c3;
    int p0, gi;
};
__device__ __forceinline__ GJ4 gj4_pre(const float* __restrict__ Asrc, int gi,
                                       int p0, int lda) {
    GJ4 s; s.p0 = p0; s.gi = gi;
    const float4 R0 = *(const float4*)(Asrc + (p0+0)*lda + p0);
    const float4 R1 = *(const float4*)(Asrc + (p0+1)*lda + p0);
    const float4 R2 = *(const float4*)(Asrc + (p0+2)*lda + p0);
    const float4 R3 = *(const float4*)(Asrc + (p0+3)*lda + p0);
    const float4 Ci = *(const float4*)(Asrc + gi*lda + p0);
    s.inv0 = __fdividef(1.f, R0.x);
    float u01 = R0.y*s.inv0, u02 = R0.z*s.inv0, u03 = R0.w*s.inv0;
    s.P10 = R1.x;
    float a11 = fmaf(-R1.x, u01, R1.y);  s.inv1 = __fdividef(1.f, a11);
    float a12 = fmaf(-R1.x, u02, R1.z), a13 = fmaf(-R1.x, u03, R1.w);
    float v12 = a12*s.inv1, v13 = a13*s.inv1;
    s.P20 = R2.x;
    s.a21 = fmaf(-R2.x, u01, R2.y);
    float a22 = fmaf(-s.a21, v12, fmaf(-R2.x, u02, R2.z));
    s.inv2 = __fdividef(1.f, a22);
    float a23 = fmaf(-s.a21, v13, fmaf(-R2.x, u03, R2.w));
    float w23 = a23*s.inv2;
    s.P30 = R3.x;
    s.a31 = fmaf(-R3.x, u01, R3.y);
    s.a32 = fmaf(-s.a31, v12, fmaf(-R3.x, u02, R3.z));
    float a33 = fmaf(-s.a32, w23, fmaf(-s.a31, v13, fmaf(-R3.x, u03, R3.w)));
    s.inv3 = __fdividef(1.f, a33);
    s.c0 = Ci.x;
    s.c1 = (gi==p0)   ? u01 : fmaf(-s.c0, u01, Ci.y);
    float c2t = (gi==p0)   ? u02 : fmaf(-s.c0, u02, Ci.z);
    s.c2 = (gi==p0+1) ? v12 : fmaf(-s.c1, v12, c2t);
    float c3t = (gi==p0)   ? u03 : fmaf(-s.c0, u03, Ci.w);
    float c3u = (gi==p0+1) ? v13 : fmaf(-s.c1, v13, c3t);
    s.c3 = (gi==p0+2) ? w23 : fmaf(-s.c2, w23, c3u);
    return s;
}
__device__ __forceinline__ float4 gj4_col4(const GJ4& s, const float* __restrict__ Asrc,
                                           int jj, int lda) {
    const int p0 = s.p0, gi = s.gi;
    float4 m0 = *(const float4*)(Asrc + (p0+0)*lda + jj);
    float4 m1 = *(const float4*)(Asrc + (p0+1)*lda + jj);
    float4 m2 = *(const float4*)(Asrc + (p0+2)*lda + jj);
    float4 m3 = *(const float4*)(Asrc + (p0+3)*lda + jj);
    float4 mi = *(const float4*)(Asrc + gi*lda + jj);
    float4 r0 = f4scale(m0, s.inv0);
    float4 E  = (gi==p0)   ? r0 : f4fma(-s.c0, r0, mi);
    float4 t1 = f4fma(-s.P10, r0, m1);
    float4 r1 = f4scale(t1, s.inv1);
    E = (gi==p0+1) ? r1 : f4fma(-s.c1, r1, E);
    float4 t2 = f4fma(-s.a21, r1, f4fma(-s.P20, r0, m2));
    float4 r2 = f4scale(t2, s.inv2);
    E = (gi==p0+2) ? r2 : f4fma(-s.c2, r2, E);
    float4 t3 = f4fma(-s.a32, r2, f4fma(-s.a31, r1, f4fma(-s.P30, r0, m3)));
    float4 r3 = f4scale(t3, s.inv3);
    E = (gi==p0+3) ? r3 : f4fma(-s.c3, r3, E);
    return E;
}

__global__ __launch_bounds__(NT, 1)
void lgssm_kernel(const float* __restrict__ g_a,   const float* __restrict__ g_alpha,
                  const float* __restrict__ g_u,   const float* __restrict__ g_A,
                  const float* __restrict__ g_B,   const float* __restrict__ g_C,
                  const float* __restrict__ g_lQ,  const float* __restrict__ g_lR,
                  const float* __restrict__ g_z0m, const float* __restrict__ g_z0lv,
                  float* __restrict__ out)
{
    extern __shared__ float sh[];
    float* sAm  = sh + O_SAM;
    float* sBm  = sh + O_SBM;
    float* sCm  = sh + O_SCM;
    float* pA   = sh + O_A;
    float* pAtr = sh + O_ATR;
    float* pCm  = sh + O_CM;
    float* pCtr = sh + O_CTR;
    float* zc   = sh + O_ZC;
    float* tmpM = sh + O_TMP;
    float* pPp  = sh + O_PP;
    float* pCPm = sh + O_CPM;
    float* aug0 = sh + O_AUG0;
    float* aug1 = sh + O_AUG1;
    float* augS0= sh + O_AGS0;
    float* augS1= sh + O_AGS1;
    float* KT2  = sh + O_KT2;
    float* fcS  = sh + O_FCS;
    float* fmS  = sh + O_FMS;
    float* Ybuf = sh + O_YB;
    float* YtrB = sh + O_YT;
    float* NbS  = sh + O_NB;
    float* zpS  = sh + O_ZPS;
    float* zm   = sh + O_ZM;
    float* zm2  = sh + O_ZM2;
    float* alB  = sh + O_AL;
    float* suB  = sh + O_SU;
    float* saB  = sh + O_SA;
    float* apred= sh + O_AP;
    float* dz   = sh + O_DZ;
    float* qd   = sh + O_QD;
    float* rd   = sh + O_RD;
    float* CAtr = sh + O_CAT;
    float* CQC  = sh + O_CQC;

    const int tid = threadIdx.x;
    const int b   = blockIdx.x;
    const int i4  = tid >> 3;          // 0..31 for tid<256
    const int j4  = (tid & 7) << 2;    // 0,4..28
    const int r0  = tid >> 3;          // row pair base (tid<128 -> 0..15)
    const int r1  = r0 + 16;

    // ---- preload constants, noise diagonals, t=0 inputs, init state ----
    for (int idx = tid; idx < 8192; idx += NT) sAm[idx] = g_A[idx];
    for (int idx = tid; idx < 8192; idx += NT) sBm[idx] = g_B[idx];
    for (int idx = tid; idx < 4096; idx += NT) sCm[idx] = g_C[idx];
    if (tid < 32) qd[tid] = expf(g_lQ[tid]);
    if (tid < 16) rd[tid] = expf(g_lR[tid]);
    {
        const size_t ib0 = (size_t)b * TLEN;
        if (tid < 8)  alB[tid] = g_alpha[ib0 * 8  + tid];
        if (tid < 32) suB[tid] = g_u    [ib0 * 32 + tid];
        if (tid < 16) saB[tid] = g_a    [ib0 * 16 + tid];
        if (tid < 32) { zm[tid] = g_z0m[tid]; zm2[tid] = g_z0m[tid]; }
        if (tid < 256) {
            float4 v = make_float4(0.f, 0.f, 0.f, 0.f);
            int d = i4 - j4;
            if (d >= 0 && d < 4) ((float*)&v)[d] = expf(g_z0lv[i4]);
            *(float4*)(pPp + i4 * LD + j4) = v;   // Ppred at t=0 = prior cov
        }
    }
    __syncthreads();

    // =============== FORWARD FILTER (also produces Y, N, zpred) ===============
    #pragma unroll 1
    for (int t = 0; t < TLEN; ++t) {
        const size_t ib = (size_t)b * TLEN + t;
        const int pb = t & 1, nb = pb ^ 1;
        const bool hasnext = (t + 1 < TLEN);

        // prefetch next step's inputs (high threads, stored in GJ phase 0)
        float pfa = 0.f, pfu = 0.f, pfo = 0.f;
        if (hasnext) {
            if (tid >= 448 && tid < 456) pfa = g_alpha[(ib + 1) * 8  + (tid - 448)];
            if (tid >= 456 && tid < 472) pfo = g_a    [(ib + 1) * 16 + (tid - 456)];
            if (tid >= 472 && tid < 504) pfu = g_u    [(ib + 1) * 32 + (tid - 472)];
        }

        // ---- P0: mixtures A, A^T, B(tmpM), C, C^T ----
        if (tid < 256) {
            const float* al = alB + pb * 8;
            float4 aa = make_float4(0.f,0.f,0.f,0.f);
            float4 bb = make_float4(0.f,0.f,0.f,0.f);
            #pragma unroll
            for (int k = 0; k < 8; ++k) {
                const float w = al[k];
                float4 m = *(const float4*)(sAm + k * 1024 + i4 * 32 + j4);
                FMA4S(aa, w, m);
                m = *(const float4*)(sBm + k * 1024 + i4 * 32 + j4);
                FMA4S(bb, w, m);
            }
            *(float4*)(pA + i4 * LD + j4) = aa;
            pAtr[(j4+0)*LD + i4] = aa.x; pAtr[(j4+1)*LD + i4] = aa.y;
            pAtr[(j4+2)*LD + i4] = aa.z; pAtr[(j4+3)*LD + i4] = aa.w;
            *(float4*)(tmpM + i4 * LD + j4) = bb;
        } else {
            const int ii = i4 - 32;
            if (ii < 16) {
                const float* al = alB + pb * 8;
                float4 cc = make_float4(0.f,0.f,0.f,0.f);
                #pragma unroll
                for (int k = 0; k < 8; ++k) {
                    const float w = al[k];
                    float4 m = *(const float4*)(sCm + k * 512 + ii * 32 + j4);
                    FMA4S(cc, w, m);
                }
                *(float4*)(pCm + ii * LD + j4) = cc;
                pCtr[(j4+0)*LDCT + ii] = cc.x; pCtr[(j4+1)*LDCT + ii] = cc.y;
                pCtr[(j4+2)*LDCT + ii] = cc.z; pCtr[(j4+3)*LDCT + ii] = cc.w;
            }
        }
        __syncthreads();

        // ---- P1: N = A zc (2x4, 128 thr) || CA = C·A (128 thr) ||
        //          CQC = C diag(q) C^T (64 thr) || zm2 + STG zpred (warp 15) ----
        if (t > 0) {
            if (tid < 128) {
                float4 o0, o1;
                mm24(pA + r0*LD, pA + r1*LD, zc, LD, j4, o0, o1);
                *(float4*)(aug0 + r0*LDA + 32 + j4) = o0;
                *(float4*)(aug0 + r1*LDA + 32 + j4) = o1;
                *(float4*)(g_Nm + (ib-1)*1024 + r0*32 + j4) = o0;
                *(float4*)(g_Nm + (ib-1)*1024 + r1*32 + j4) = o1;
            } else if (tid < 256) {
                const int idx = tid - 128;
                const int ci = idx >> 3, cj = (idx & 7) << 2;
                float4 ca = mm4(pCm + ci*LD, pA, LD, cj);
                CAtr[(cj+0)*LDCT + ci] = ca.x; CAtr[(cj+1)*LDCT + ci] = ca.y;
                CAtr[(cj+2)*LDCT + ci] = ca.z; CAtr[(cj+3)*LDCT + ci] = ca.w;
            } else if (tid < 320) {
                const int idx = tid - 256;
                const int qi = idx >> 2, qj = (idx & 3) << 2;
                float4 acc = make_float4(0.f,0.f,0.f,0.f);
                #pragma unroll
                for (int k0 = 0; k0 < 32; k0 += 4) {
                    float4 c4 = *(const float4*)(pCm + qi*LD + k0);
                    float4 q4 = *(const float4*)(qd + k0);
                    float4 bq;
                    bq = *(const float4*)(pCtr + (k0+0)*LDCT + qj); FMA4S(acc, c4.x*q4.x, bq);
                    bq = *(const float4*)(pCtr + (k0+1)*LDCT + qj); FMA4S(acc, c4.y*q4.y, bq);
                    bq = *(const float4*)(pCtr + (k0+2)*LDCT + qj); FMA4S(acc, c4.z*q4.z, bq);
                    bq = *(const float4*)(pCtr + (k0+3)*LDCT + qj); FMA4S(acc, c4.w*q4.w, bq);
                }
                *(float4*)(CQC + qi*LDCT + qj) = acc;
            } else if (tid >= 480) {
                const int i = tid - 480;
                const float* su = suB + pb * 32;
                float4 s4 = make_float4(0.f,0.f,0.f,0.f);
                #pragma unroll
                for (int k0 = 0; k0 < 32; k0 += 4) {
                    float4 m4 = *(const float4*)(tmpM + i * LD + k0);
                    float4 v4 = *(const float4*)(su + k0);
                    FMA4L(s4, m4, v4);
                    m4 = *(const float4*)(pA + i * LD + k0);
                    v4 = *(const float4*)(zm + k0);
                    FMA4L(s4, m4, v4);
                }
                float zp = (s4.x + s4.y) + (s4.z + s4.w);
                zm2[i] = zp;
                g_zp[(ib - 1) * 32 + i] = zp;
            }
        }
        __syncthreads();

        // ---- P2: Ppred = N A^T + Q (2x4) || CN = C·N (128 thr) ;
        //          t==0: M = C·P0 ----
        if (t > 0) {
            if (tid < 128) {
                float4 o0, o1;
                mm24(aug0 + r0*LDA + 32, aug0 + r1*LDA + 32, pAtr, LD, j4, o0, o1);
                int d0 = r0 - j4;
                if (d0 >= 0 && d0 < 4) ((float*)&o0)[d0] += qd[r0];
                int d1 = r1 - j4;
                if (d1 >= 0 && d1 < 4) ((float*)&o1)[d1] += qd[r1];
                *(float4*)(pPp + r0*LD + j4) = o0;
                *(float4*)(pPp + r1*LD + j4) = o1;
                *(float4*)(aug0 + r0*LDA + j4) = o0;
                *(float4*)(aug0 + r1*LDA + j4) = o1;
            } else if (tid < 256) {
                const int idx = tid - 128;
                const int ci = idx >> 3, cj = (idx & 7) << 2;
                float4 cn = mm4(pCm + ci*LD, aug0 + 32, LDA, cj);
                *(float4*)(tmpM + ci*LD + cj) = cn;
            }
        } else {
            if (tid < 128) {
                const int i = tid >> 3;
                float4 m = mm4(pCm + i*LD, pPp, LD, j4);
                *(float4*)(pCPm + i*LD + j4) = m;
                *(float4*)(augS0 + i*LDS2 + 16 + j4) = m;
            }
        }
        __syncthreads();

        // ---- P3: M = CN·A^T + C diag(q) (128 thr) || S = CN·CA^T + CQC + R
        //          (64 thr) ; t==0: S = M·C^T + R ; apred (all t) ----
        if (t > 0) {
            if (tid < 128) {
                const int i = tid >> 3;
                float4 m = mm4(tmpM + i*LD, pAtr, LD, j4);
                float4 c4 = *(const float4*)(pCm + i*LD + j4);
                float4 q4 = *(const float4*)(qd + j4);
                m.x = fmaf(c4.x, q4.x, m.x); m.y = fmaf(c4.y, q4.y, m.y);
                m.z = fmaf(c4.z, q4.z, m.z); m.w = fmaf(c4.w, q4.w, m.w);
                *(float4*)(pCPm + i*LD + j4) = m;
                *(float4*)(augS0 + i*LDS2 + 16 + j4) = m;
            } else if (tid < 192) {
                const int idx = tid - 128;
                const int i = idx >> 2, jj = (idx & 3) << 2;
                float4 s = mm4(tmpM + i*LD, CAtr, LDCT, jj);
                float4 cq = *(const float4*)(CQC + i*LDCT + jj);
                s.x += cq.x; s.y += cq.y; s.z += cq.z; s.w += cq.w;
                int d = i - jj;
                if (d >= 0 && d < 4) ((float*)&s)[d] += rd[i];
                *(float4*)(augS0 + i*LDS2 + jj) = s;
            }
        } else {
            if (tid < 64) {
                const int i = tid >> 2, jj = (tid & 3) << 2;
                float4 s = mm4(pCPm + i*LD, pCtr, LDCT, jj);
                int d = i - jj;
                if (d >= 0 && d < 4) ((float*)&s)[d] += rd[i];
                *(float4*)(augS0 + i*LDS2 + jj) = s;
            }
        }
        if (tid >= 480 && tid < 496) {
            const int i = tid - 480;
            float4 s4 = make_float4(0.f,0.f,0.f,0.f);
            #pragma unroll
            for (int k0 = 0; k0 < 32; k0 += 4) {
                float4 m4 = *(const float4*)(pCm + i * LD + k0);
                float4 v4 = *(const float4*)(zm2 + k0);
                FMA4L(s4, m4, v4);
            }
            apred[i] = (s4.x + s4.y) + (s4.z + s4.w);
        }
        __syncthreads();

        // ---- GJ: Y-solve (32 piv, 8 phases, thr<256) + S-solve (16 piv,
        //          phases 0-3, thr 256-447) + dz/prefetch (thr 448+) ----
        {
            float* Ys = aug0; float* Yd = aug1;
            float* Ss = augS0; float* Sd = augS1;
            const int yi  = tid >> 3;
            const int yjA = (tid & 7) << 2;
            const int yjB = yjA + 32;
            const int sidx = tid - 256;
            const int si = sidx & 15;
            const int sj = (sidx >> 4) << 2;
            #pragma unroll
            for (int pp = 0; pp < 8; ++pp) {
                if (tid < 256) {
                    if (t > 0) {
                        GJ4 s = gj4_pre(Ys, yi, pp << 2, LDA);
                        float4 EB = gj4_col4(s, Ys, yjB, LDA);
                        if (pp < 7) {
                            float4 EA = gj4_col4(s, Ys, yjA, LDA);
                            *(float4*)(Yd + yi * LDA + yjA) = EA;
                            *(float4*)(Yd + yi * LDA + yjB) = EB;
                        } else {
                            *(float4*)(g_Y + (ib-1)*1024 + yi*32 + (yjB-32)) = EB;
                        }
                    }
                } else if (sidx >= 0 && sidx < 192 && pp < 4) {
                    if (pp < 3 || sj >= 16) {
                        GJ4 s = gj4_pre(Ss, si, pp << 2, LDS2);
                        float4 E = gj4_col4(s, Ss, sj, LDS2);
                        if (pp < 3) {
                            *(float4*)(Sd + si * LDS2 + sj) = E;
                        } else {
                            KT2[(sj-16+0)*LDK + si] = E.x;
                            KT2[(sj-16+1)*LDK + si] = E.y;
                            KT2[(sj-16+2)*LDK + si] = E.z;
                            KT2[(sj-16+3)*LDK + si] = E.w;
                        }
                    }
                } else if (pp == 0) {
                    if (hasnext) {
                        if (tid >= 448 && tid < 456) alB[nb*8  + (tid-448)] = pfa;
                        if (tid >= 456 && tid < 472) saB[nb*16 + (tid-456)] = pfo;
                        if (tid >= 472 && tid < 504) suB[nb*32 + (tid-472)] = pfu;
                    }
                } else if (pp == 1) {
                    if (tid >= 448 && tid < 464) {
                        const int j = tid - 448;
                        dz[j] = saB[pb * 16 + j] - apred[j];
                    }
                }
                float* w;
                w = Ys; Ys = Yd; Yd = w;
                w = Ss; Ss = Sd; Sd = w;
                if (pp < 7) __syncthreads();
            }
        }
        // KT2[i][r] = Kg[i][r] ; Y STG'd from registers in phase 7

        // ---- P13: measurement update + filtered output ----
        {
            const size_t ob = ib * 2112;
            if (tid < 128) {
                float4 acc0 = *(const float4*)(pPp + r0*LD + j4);
                float4 acc1 = *(const float4*)(pPp + r1*LD + j4);
                #pragma unroll
                for (int rr = 0; rr < 16; rr += 4) {
                    float4 k0 = *(const float4*)(KT2 + r0*LDK + rr);
                    float4 k1 = *(const float4*)(KT2 + r1*LDK + rr);
                    float4 m;
                    m = *(const float4*)(pCPm + (rr+0)*LD + j4);
                    acc0 = f4fma(-k0.x, m, acc0); acc1 = f4fma(-k1.x, m, acc1);
                    m = *(const float4*)(pCPm + (rr+1)*LD + j4);
                    acc0 = f4fma(-k0.y, m, acc0); acc1 = f4fma(-k1.y, m, acc1);
                    m = *(const float4*)(pCPm + (rr+2)*LD + j4);
                    acc0 = f4fma(-k0.z, m, acc0); acc1 = f4fma(-k1.z, m, acc1);
                    m = *(const float4*)(pCPm + (rr+3)*LD + j4);
                    acc0 = f4fma(-k0.w, m, acc0); acc1 = f4fma(-k1.w, m, acc1);
                }
                *(float4*)(zc + r0*LD + j4) = acc0;
                *(float4*)(zc + r1*LD + j4) = acc1;
                *(float4*)(out + ob + 32 + r0*32 + j4) = acc0;
                *(float4*)(out + ob + 32 + r1*32 + j4) = acc1;
                if (t == TLEN - 1) {
                    *(float4*)(out + ob + 1088 + r0*32 + j4) = acc0;
                    *(float4*)(out + ob + 1088 + r1*32 + j4) = acc1;
                }
            } else if (tid >= 480) {
                const int i = tid - 480;
                float4 s4 = make_float4(0.f,0.f,0.f,0.f);
                #pragma unroll
                for (int rr = 0; rr < 16; rr += 4) {
                    float4 k4 = *(const float4*)(KT2 + i * LDK + rr);
                    float4 d4 = *(const float4*)(dz + rr);
                    FMA4L(s4, k4, d4);
                }
                float nm = zm2[i] + (s4.x + s4.y) + (s4.z + s4.w);
                zm[i] = nm;
                out[ob + i] = nm;
                if (t == TLEN - 1) out[ob + 1056 + i] = nm;
            }
        }
        // no trailing barrier: next P0-end barrier orders everything
    }

    // =============== BACKWARD RTS SMOOTHER (2 phases/step) ===============
    __syncthreads();
    {   // preload slot TLEN-2 into parity 0
        const size_t slot0 = (size_t)b * TLEN + (TLEN - 2);
        if (tid < 256) {
            float4 y = *(const float4*)(g_Y  + slot0 * 1024 + i4 * 32 + j4);
            float4 n = *(const float4*)(g_Nm + slot0 * 1024 + i4 * 32 + j4);
            *(float4*)(Ybuf + i4 * LD + j4) = y;
            YtrB[(j4+0)*LD + i4] = y.x; YtrB[(j4+1)*LD + i4] = y.y;
            YtrB[(j4+2)*LD + i4] = y.z; YtrB[(j4+3)*LD + i4] = y.w;
            *(float4*)(NbS + i4 * LD + j4) = n;
            *(float4*)(fcS + i4 * LD + j4) =
                *(const float4*)(out + slot0 * 2112 + 32 + i4 * 32 + j4);
        }
        if (tid < 32) {
            zpS[tid] = g_zp[slot0 * 32 + tid];
            fmS[tid] = out[slot0 * 2112 + tid];
        }
    }
    __syncthreads();

    #pragma unroll 1
    for (int t = TLEN - 2; t >= 0; --t) {
        const size_t ib = (size_t)b * TLEN + t;
        const size_t ob = ib * 2112;
        const int pb = t & 1;
        const int nb = pb ^ 1;
        const bool hasprev = (t > 0);

        // prefetch slot t-1 (threads 256-511)
        float4 pfY = make_float4(0.f,0.f,0.f,0.f);
        float4 pfN = make_float4(0.f,0.f,0.f,0.f);
        float4 pfc = make_float4(0.f,0.f,0.f,0.f);
        float pfz = 0.f, pfm = 0.f;
        int pi = 0, pj = 0;
        if (tid >= 256) { const int idx = tid - 256; pi = idx >> 3; pj = (idx & 7) << 2; }
        if (hasprev) {
            const size_t sp = ib - 1;
            if (tid >= 256) {
                pfY = *(const float4*)(g_Y  + sp * 1024 + pi * 32 + pj);
                pfN = *(const float4*)(g_Nm + sp * 1024 + pi * 32 + pj);
                pfc = *(const float4*)(out + sp * 2112 + 32 + pi * 32 + pj);
            }
            if (tid >= 448 && tid < 480) {
                pfz = g_zp[sp * 32 + (tid - 448)];
                pfm = out[sp * 2112 + (tid - 448)];
            }
        }

        // ---- PW: W = Ps·Y - N (2x4, 128 thr) ; zs2 (warp 15) ----
        if (tid < 128) {
            float4 o0, o1;
            mm24(zc + r0*LD, zc + r1*LD, Ybuf + pb*1152, LD, j4, o0, o1);
            float4 n0 = *(const float4*)(NbS + pb*1152 + r0*LD + j4);
            float4 n1 = *(const float4*)(NbS + pb*1152 + r1*LD + j4);
            o0.x -= n0.x; o0.y -= n0.y; o0.z -= n0.z; o0.w -= n0.w;
            o1.x -= n1.x; o1.y -= n1.y; o1.z -= n1.z; o1.w -= n1.w;
            *(float4*)(aug1 + r0*LDA + j4) = o0;
            *(float4*)(aug1 + r1*LDA + j4) = o1;
        } else if (tid >= 480) {
            const int i = tid - 480;
            float4 s4 = make_float4(0.f,0.f,0.f,0.f);
            #pragma unroll
            for (int k0 = 0; k0 < 32; k0 += 4) {
                float4 y4 = *(const float4*)(YtrB + pb*1152 + i*LD + k0);
                float4 z4 = *(const float4*)(zm + k0);
                float4 p4 = *(const float4*)(zpS + pb*32 + k0);
                float4 d4 = make_float4(z4.x-p4.x, z4.y-p4.y, z4.z-p4.z, z4.w-p4.w);
                FMA4L(s4, y4, d4);
            }
            zm2[i] = fmS[pb*32 + i] + (s4.x + s4.y) + (s4.z + s4.w);
        }
        __syncthreads();

        // ---- P21: Ps = fc + Ytr·W (2x4) ; outputs ; store prefetch [nb] ----
        if (tid < 128) {
            float4 w0, w1;
            mm24(YtrB + pb*1152 + r0*LD, YtrB + pb*1152 + r1*LD, aug1, LDA, j4, w0, w1);
            float4 f0 = *(const float4*)(fcS + pb*1152 + r0*LD + j4);
            float4 f1 = *(const float4*)(fcS + pb*1152 + r1*LD + j4);
            f0.x += w0.x; f0.y += w0.y; f0.z += w0.z; f0.w += w0.w;
            f1.x += w1.x; f1.y += w1.y; f1.z += w1.z; f1.w += w1.w;
            *(float4*)(zc + r0*LD + j4) = f0;
            *(float4*)(zc + r1*LD + j4) = f1;
            *(float4*)(out + ob + 1088 + r0*32 + j4) = f0;
            *(float4*)(out + ob + 1088 + r1*32 + j4) = f1;
        }
        if (tid >= 256 && hasprev) {
            *(float4*)(Ybuf + nb*1152 + pi*LD + pj) = pfY;
            YtrB[nb*1152 + (pj+0)*LD + pi] = pfY.x;
            YtrB[nb*1152 + (pj+1)*LD + pi] = pfY.y;
            YtrB[nb*1152 + (pj+2)*LD + pi] = pfY.z;
            YtrB[nb*1152 + (pj+3)*LD + pi] = pfY.w;
            *(float4*)(NbS + nb*1152 + pi*LD + pj) = pfN;
            *(float4*)(fcS + nb*1152 + pi*LD + pj) = pfc;
        }
        if (tid >= 448 && tid < 480) {
            const int i = tid - 448;
            float nm = zm2[i];
            zm[i] = nm;
            out[ob + 1056 + i] = nm;
            if (hasprev) {
                zpS[nb*32 + i] = pfz;
                fmS[nb*32 + i] = pfm;
            }
        }
        __syncthreads();
    }
}

extern "C" void kernel_launch(void* const* d_in, const int* in_sizes, int n_in,
                              void* d_out, int out_size) {
    const float* g_a    = (const float*)d_in[0];
    const float* g_alpha= (const float*)d_in[1];
    const float* g_u    = (const float*)d_in[2];
    const float* g_A    = (const float*)d_in[3];
    const float* g_B    = (const float*)d_in[4];
    const float* g_C    = (const float*)d_in[5];
    const float* g_lQ   = (const float*)d_in[6];
    const float* g_lR   = (const float*)d_in[7];
    const float* g_z0m  = (const float*)d_in[8];
    const float* g_z0lv = (const float*)d_in[9];
    float* out = (float*)d_out;
    int B = in_sizes[0] / (TLEN * 16);
    size_t smem = SMEM_FLOATS * sizeof(float);
    cudaFuncSetAttribute(lgssm_kernel, cudaFuncAttributeMaxDynamicSharedMemorySize, (int)smem);
    lgssm_kernel<<<B, NT, smem>>>(g_a, g_alpha, g_u, g_A, g_B, g_C,
                                  g_lQ, g_lR, g_z0m, g_z0lv, out);
}

// round 11
// speedup vs baseline: 2.3817x; 1.0435x over previous
#include <cuda_runtime.h>

#define NT     512
#define TLEN   512
#define LD     36     // padded leading dim, 32-col matrices
#define LDA    68     // Y-augmented GJ matrix leading dim (32x64)
#define LDS2   52     // S-augmented GJ matrix leading dim (16x48)
#define LDCT   20     // C^T / CA^T / CQC leading dim
#define LDK    20     // KT2 leading dim
#define MAXB   128

// scratch: smoother gains & predicted stats produced in forward pass
__device__ float g_Y [MAXB * TLEN * 1024];
__device__ float g_Nm[MAXB * TLEN * 1024];
__device__ float g_zp[MAXB * TLEN * 32];

// ---- shared memory layout (float offsets) ----
#define O_SAM  0
#define O_SBM  8192
#define O_SCM  16384
#define O_A    20480   // 32xLD A_t
#define O_ATR  21632   // 32xLD A_t^T
#define O_CM   22784   // 16xLD C_t
#define O_CTR  23360   // 32xLDCT C_t^T
#define O_ZC   24000   // 32xLD covariance state (filtered / Ps)
#define O_TMP  25152   // 32xLD B mixture (P2+: CN in rows 0-15)
#define O_PP   26304   // 32xLD Ppred
#define O_CPM  27456   // 16xLD M
#define O_AUG0 28032   // 32xLDA Y-GJ buffer 0
#define O_AUG1 30208   // 32xLDA Y-GJ buffer 1 (bwd: W)
#define O_AGS0 32384   // 16xLDS2 S-GJ buffer 0
#define O_AGS1 33216   // 16xLDS2 S-GJ buffer 1
#define O_KT2  34048   // 32xLDK Kg (row i, col r)
#define O_FCS  34688   // 2 x 1152 filtered cov (parity)
#define O_FMS  36992   // 2 x 32
#define O_YB   37056   // 2 x 1152 Y (parity)
#define O_YT   39360   // 2 x 1152 Y^T (parity)
#define O_NB   41664   // 2 x 1152 N (parity)
#define O_ZPS  43968   // 2 x 32 zpred (parity)
#define O_ZM   44032   // 32
#define O_ZM2  44064   // 32
#define O_AL   44096   // 2 x 8
#define O_SU   44112   // 2 x 32
#define O_SA   44176   // 2 x 16
#define O_AP   44208   // 16
#define O_DZ   44224   // 32
#define O_QD   44256   // 32
#define O_RD   44288   // 16
#define O_CAT  44304   // 32xLDCT  CA^T
#define O_CQC  44944   // 16xLDCT  C diag(q) C^T
#define SMEM_FLOATS 45264

__device__ __forceinline__ float4 f4fma(float s, float4 b, float4 a) {
    return make_float4(fmaf(s,b.x,a.x), fmaf(s,b.y,a.y), fmaf(s,b.z,a.z), fmaf(s,b.w,a.w));
}
__device__ __forceinline__ float4 f4scale(float4 a, float s) {
    return make_float4(a.x*s, a.y*s, a.z*s, a.w*s);
}
#define FMA4S(acc, s, b)                                                      \
    acc.x = fmaf((s), (b).x, acc.x); acc.y = fmaf((s), (b).y, acc.y);         \
    acc.z = fmaf((s), (b).z, acc.z); acc.w = fmaf((s), (b).w, acc.w);
#define FMA4L(s4, m4, v4)                                                     \
    s4.x = fmaf(m4.x, v4.x, s4.x); s4.y = fmaf(m4.y, v4.y, s4.y);             \
    s4.z = fmaf(m4.z, v4.z, s4.z); s4.w = fmaf(m4.w, v4.w, s4.w);

__device__ __forceinline__ float4 mm4(const float* __restrict__ rowA,
                                      const float* __restrict__ matB,
                                      const int ldB, const int jj) {
    float4 a0 = make_float4(0.f,0.f,0.f,0.f);
    float4 a1 = make_float4(0.f,0.f,0.f,0.f);
    #pragma unroll
    for (int k0 = 0; k0 < 32; k0 += 8) {
        float4 x = *(const float4*)(rowA + k0);
        float4 y = *(const float4*)(rowA + k0 + 4);
        const float* Bp = matB + k0 * ldB + jj;
        float4 b;
        b = *(const float4*)(Bp);           FMA4S(a0, x.x, b);
        b = *(const float4*)(Bp + ldB);     FMA4S(a1, x.y, b);
        b = *(const float4*)(Bp + 2*ldB);   FMA4S(a0, x.z, b);
        b = *(const float4*)(Bp + 3*ldB);   FMA4S(a1, x.w, b);
        b = *(const float4*)(Bp + 4*ldB);   FMA4S(a0, y.x, b);
        b = *(const float4*)(Bp + 5*ldB);   FMA4S(a1, y.y, b);
        b = *(const float4*)(Bp + 6*ldB);   FMA4S(a0, y.z, b);
        b = *(const float4*)(Bp + 7*ldB);   FMA4S(a1, y.w, b);
    }
    return make_float4(a0.x + a1.x, a0.y + a1.y, a0.z + a1.z, a0.w + a1.w);
}

// two rows x 4 cols: B loads shared between the rows
__device__ __forceinline__ void mm24(const float* __restrict__ rA0,
                                     const float* __restrict__ rA1,
                                     const float* __restrict__ matB,
                                     const int ldB, const int jj,
                                     float4& o0, float4& o1) {
    float4 a0 = make_float4(0.f,0.f,0.f,0.f);
    float4 a1 = make_float4(0.f,0.f,0.f,0.f);
    float4 c0 = make_float4(0.f,0.f,0.f,0.f);
    float4 c1 = make_float4(0.f,0.f,0.f,0.f);
    #pragma unroll
    for (int k0 = 0; k0 < 32; k0 += 4) {
        float4 x = *(const float4*)(rA0 + k0);
        float4 y = *(const float4*)(rA1 + k0);
        const float* Bp = matB + k0 * ldB + jj;
        float4 b;
        b = *(const float4*)(Bp);         FMA4S(a0, x.x, b); FMA4S(c0, y.x, b);
        b = *(const float4*)(Bp + ldB);   FMA4S(a1, x.y, b); FMA4S(c1, y.y, b);
        b = *(const float4*)(Bp + 2*ldB); FMA4S(a0, x.z, b); FMA4S(c0, y.z, b);
        b = *(const float4*)(Bp + 3*ldB); FMA4S(a1, x.w, b); FMA4S(c1, y.w, b);
    }
    o0 = make_float4(a0.x+a1.x, a0.y+a1.y, a0.z+a1.z, a0.w+a1.w);
    o1 = make_float4(c0.x+c1.x, c0.y+c1.y, c0.z+c1.z, c0.w+c1.w);
}

// ---- 4-pivot Gauss-Jordan block state ----
struct GJ4 {
    float inv0, inv1, inv2, inv3;
    float P10, P20, P30, a21, a31, a32;
    float c0, c1, c2, c3;
    int p0, gi;
};
__device__ __forceinline__ GJ4 gj4_pre(const float* __restrict__ Asrc, int gi,
                                       int p0, int lda) {
    GJ4 s; s.p0 = p0; s.gi = gi;
    const float4 R0 = *(const float4*)(Asrc + (p0+0)*lda + p0);
    const float4 R1 = *(const float4*)(Asrc + (p0+1)*lda + p0);
    const float4 R2 = *(const float4*)(Asrc + (p0+2)*lda + p0);
    const float4 R3 = *(const float4*)(Asrc + (p0+3)*lda + p0);
    const float4 Ci = *(const float4*)(Asrc + gi*lda + p0);
    s.inv0 = __fdividef(1.f, R0.x);
    float u01 = R0.y*s.inv0, u02 = R0.z*s.inv0, u03 = R0.w*s.inv0;
    s.P10 = R1.x;
    float a11 = fmaf(-R1.x, u01, R1.y);  s.inv1 = __fdividef(1.f, a11);
    float a12 = fmaf(-R1.x, u02, R1.z), a13 = fmaf(-R1.x, u03, R1.w);
    float v12 = a12*s.inv1, v13 = a13*s.inv1;
    s.P20 = R2.x;
    s.a21 = fmaf(-R2.x, u01, R2.y);
    float a22 = fmaf(-s.a21, v12, fmaf(-R2.x, u02, R2.z));
    s.inv2 = __fdividef(1.f, a22);
    float a23 = fmaf(-s.a21, v13, fmaf(-R2.x, u03, R2.w));
    float w23 = a23*s.inv2;
    s.P30 = R3.x;
    s.a31 = fmaf(-R3.x, u01, R3.y);
    s.a32 = fmaf(-s.a31, v12, fmaf(-R3.x, u02, R3.z));
    float a33 = fmaf(-s.a32, w23, fmaf(-s.a31, v13, fmaf(-R3.x, u03, R3.w)));
    s.inv3 = __fdividef(1.f, a33);
    s.c0 = Ci.x;
    s.c1 = (gi==p0)   ? u01 : fmaf(-s.c0, u01, Ci.y);
    float c2t = (gi==p0)   ? u02 : fmaf(-s.c0, u02, Ci.z);
    s.c2 = (gi==p0+1) ? v12 : fmaf(-s.c1, v12, c2t);
    float c3t = (gi==p0)   ? u03 : fmaf(-s.c0, u03, Ci.w);
    float c3u = (gi==p0+1) ? v13 : fmaf(-s.c1, v13, c3t);
    s.c3 = (gi==p0+2) ? w23 : fmaf(-s.c2, w23, c3u);
    return s;
}
__device__ __forceinline__ float4 gj4_col4(const GJ4& s, const float* __restrict__ Asrc,
                                           int jj, int lda) {
    const int p0 = s.p0, gi = s.gi;
    float4 m0 = *(const float4*)(Asrc + (p0+0)*lda + jj);
    float4 m1 = *(const float4*)(Asrc + (p0+1)*lda + jj);
    float4 m2 = *(const float4*)(Asrc + (p0+2)*lda + jj);
    float4 m3 = *(const float4*)(Asrc + (p0+3)*lda + jj);
    float4 mi = *(const float4*)(Asrc + gi*lda + jj);
    float4 r0 = f4scale(m0, s.inv0);
    float4 E  = (gi==p0)   ? r0 : f4fma(-s.c0, r0, mi);
    float4 t1 = f4fma(-s.P10, r0, m1);
    float4 r1 = f4scale(t1, s.inv1);
    E = (gi==p0+1) ? r1 : f4fma(-s.c1, r1, E);
    float4 t2 = f4fma(-s.a21, r1, f4fma(-s.P20, r0, m2));
    float4 r2 = f4scale(t2, s.inv2);
    E = (gi==p0+2) ? r2 : f4fma(-s.c2, r2, E);
    float4 t3 = f4fma(-s.a32, r2, f4fma(-s.a31, r1, f4fma(-s.P30, r0, m3)));
    float4 r3 = f4scale(t3, s.inv3);
    E = (gi==p0+3) ? r3 : f4fma(-s.c3, r3, E);
    return E;
}

__global__ __launch_bounds__(NT, 1)
void lgssm_kernel(const float* __restrict__ g_a,   const float* __restrict__ g_alpha,
                  const float* __restrict__ g_u,   const float* __restrict__ g_A,
                  const float* __restrict__ g_B,   const float* __restrict__ g_C,
                  const float* __restrict__ g_lQ,  const float* __restrict__ g_lR,
                  const float* __restrict__ g_z0m, const float* __restrict__ g_z0lv,
                  float* __restrict__ out)
{
    extern __shared__ float sh[];
    float* sAm  = sh + O_SAM;
    float* sBm  = sh + O_SBM;
    float* sCm  = sh + O_SCM;
    float* pA   = sh + O_A;
    float* pAtr = sh + O_ATR;
    float* pCm  = sh + O_CM;
    float* pCtr = sh + O_CTR;
    float* zc   = sh + O_ZC;
    float* tmpM = sh + O_TMP;
    float* pPp  = sh + O_PP;
    float* pCPm = sh + O_CPM;
    float* aug0 = sh + O_AUG0;
    float* aug1 = sh + O_AUG1;
    float* augS0= sh + O_AGS0;
    float* augS1= sh + O_AGS1;
    float* KT2  = sh + O_KT2;
    float* fcS  = sh + O_FCS;
    float* fmS  = sh + O_FMS;
    float* Ybuf = sh + O_YB;
    float* YtrB = sh + O_YT;
    float* NbS  = sh + O_NB;
    float* zpS  = sh + O_ZPS;
    float* zm   = sh + O_ZM;
    float* zm2  = sh + O_ZM2;
    float* alB  = sh + O_AL;
    float* suB  = sh + O_SU;
    float* saB  = sh + O_SA;
    float* apred= sh + O_AP;
    float* dz   = sh + O_DZ;
    float* qd   = sh + O_QD;
    float* rd   = sh + O_RD;
    float* CAtr = sh + O_CAT;
    float* CQC  = sh + O_CQC;

    const int tid = threadIdx.x;
    const int b   = blockIdx.x;
    const int i4  = tid >> 3;          // 0..31 for tid<256
    const int j4  = (tid & 7) << 2;    // 0,4..28
    const int r0  = tid >> 3;          // row-pair base for tid<128
    const int r1  = r0 + 16;

    // ---- preload constants, noise diagonals, t=0 inputs, init state ----
    for (int idx = tid; idx < 8192; idx += NT) sAm[idx] = g_A[idx];
    for (int idx = tid; idx < 8192; idx += NT) sBm[idx] = g_B[idx];
    for (int idx = tid; idx < 4096; idx += NT) sCm[idx] = g_C[idx];
    if (tid < 32) qd[tid] = expf(g_lQ[tid]);
    if (tid < 16) rd[tid] = expf(g_lR[tid]);
    {
        const size_t ib0 = (size_t)b * TLEN;
        if (tid < 8)  alB[tid] = g_alpha[ib0 * 8  + tid];
        if (tid < 32) suB[tid] = g_u    [ib0 * 32 + tid];
        if (tid < 16) saB[tid] = g_a    [ib0 * 16 + tid];
        if (tid < 32) { zm[tid] = g_z0m[tid]; zm2[tid] = g_z0m[tid]; }
        if (tid < 256) {
            float4 v = make_float4(0.f, 0.f, 0.f, 0.f);
            int d = i4 - j4;
            if (d >= 0 && d < 4) ((float*)&v)[d] = expf(g_z0lv[i4]);
            *(float4*)(pPp + i4 * LD + j4) = v;   // Ppred at t=0 = prior cov
        }
    }
    __syncthreads();

    // =============== FORWARD FILTER (also produces Y, N, zpred) ===============
    #pragma unroll 1
    for (int t = 0; t < TLEN; ++t) {
        const size_t ib = (size_t)b * TLEN + t;
        const int pb = t & 1, nb = pb ^ 1;
        const bool hasnext = (t + 1 < TLEN);

        // prefetch next step's inputs (stored at GJ phase 0)
        float pfa = 0.f, pfu = 0.f, pfo = 0.f;
        if (hasnext) {
            if (tid >= 448 && tid < 456) pfa = g_alpha[(ib + 1) * 8  + (tid - 448)];
            if (tid >= 456 && tid < 472) pfo = g_a    [(ib + 1) * 16 + (tid - 456)];
            if (tid >= 472 && tid < 504) pfu = g_u    [(ib + 1) * 32 + (tid - 472)];
        }

        // ---- P0: mixtures A, A^T, B(tmpM), C, C^T ----
        if (tid < 256) {
            const float* al = alB + pb * 8;
            float4 aa = make_float4(0.f,0.f,0.f,0.f);
            float4 bb = make_float4(0.f,0.f,0.f,0.f);
            #pragma unroll
            for (int k = 0; k < 8; ++k) {
                const float w = al[k];
                float4 m = *(const float4*)(sAm + k * 1024 + i4 * 32 + j4);
                FMA4S(aa, w, m);
                m = *(const float4*)(sBm + k * 1024 + i4 * 32 + j4);
                FMA4S(bb, w, m);
            }
            *(float4*)(pA + i4 * LD + j4) = aa;
            pAtr[(j4+0)*LD + i4] = aa.x; pAtr[(j4+1)*LD + i4] = aa.y;
            pAtr[(j4+2)*LD + i4] = aa.z; pAtr[(j4+3)*LD + i4] = aa.w;
            *(float4*)(tmpM + i4 * LD + j4) = bb;
        } else {
            const int ii = i4 - 32;
            if (ii < 16) {
                const float* al = alB + pb * 8;
                float4 cc = make_float4(0.f,0.f,0.f,0.f);
                #pragma unroll
                for (int k = 0; k < 8; ++k) {
                    const float w = al[k];
                    float4 m = *(const float4*)(sCm + k * 512 + ii * 32 + j4);
                    FMA4S(cc, w, m);
                }
                *(float4*)(pCm + ii * LD + j4) = cc;
                pCtr[(j4+0)*LDCT + ii] = cc.x; pCtr[(j4+1)*LDCT + ii] = cc.y;
                pCtr[(j4+2)*LDCT + ii] = cc.z; pCtr[(j4+3)*LDCT + ii] = cc.w;
            }
        }
        __syncthreads();

        // ---- P1: N (128) || CA (128) || CQC (64) || zm2+STG zpred (warp 15) ----
        if (t > 0) {
            if (tid < 128) {
                float4 o0, o1;
                mm24(pA + r0*LD, pA + r1*LD, zc, LD, j4, o0, o1);
                *(float4*)(aug0 + r0*LDA + 32 + j4) = o0;
                *(float4*)(aug0 + r1*LDA + 32 + j4) = o1;
                *(float4*)(g_Nm + (ib-1)*1024 + r0*32 + j4) = o0;
                *(float4*)(g_Nm + (ib-1)*1024 + r1*32 + j4) = o1;
            } else if (tid < 256) {
                const int idx = tid - 128;
                const int ci = idx >> 3, cj = (idx & 7) << 2;
                float4 ca = mm4(pCm + ci*LD, pA, LD, cj);
                CAtr[(cj+0)*LDCT + ci] = ca.x; CAtr[(cj+1)*LDCT + ci] = ca.y;
                CAtr[(cj+2)*LDCT + ci] = ca.z; CAtr[(cj+3)*LDCT + ci] = ca.w;
            } else if (tid < 320) {
                const int idx = tid - 256;
                const int qi = idx >> 2, qj = (idx & 3) << 2;
                float4 acc = make_float4(0.f,0.f,0.f,0.f);
                #pragma unroll
                for (int k0 = 0; k0 < 32; k0 += 4) {
                    float4 c4 = *(const float4*)(pCm + qi*LD + k0);
                    float4 q4 = *(const float4*)(qd + k0);
                    float4 bq;
                    bq = *(const float4*)(pCtr + (k0+0)*LDCT + qj); FMA4S(acc, c4.x*q4.x, bq);
                    bq = *(const float4*)(pCtr + (k0+1)*LDCT + qj); FMA4S(acc, c4.y*q4.y, bq);
                    bq = *(const float4*)(pCtr + (k0+2)*LDCT + qj); FMA4S(acc, c4.z*q4.z, bq);
                    bq = *(const float4*)(pCtr + (k0+3)*LDCT + qj); FMA4S(acc, c4.w*q4.w, bq);
                }
                *(float4*)(CQC + qi*LDCT + qj) = acc;
            } else if (tid >= 480) {
                const int i = tid - 480;
                const float* su = suB + pb * 32;
                float4 s4 = make_float4(0.f,0.f,0.f,0.f);
                #pragma unroll
                for (int k0 = 0; k0 < 32; k0 += 4) {
                    float4 m4 = *(const float4*)(tmpM + i * LD + k0);
                    float4 v4 = *(const float4*)(su + k0);
                    FMA4L(s4, m4, v4);
                    m4 = *(const float4*)(pA + i * LD + k0);
                    v4 = *(const float4*)(zm + k0);
                    FMA4L(s4, m4, v4);
                }
                float zp = (s4.x + s4.y) + (s4.z + s4.w);
                zm2[i] = zp;
                g_zp[(ib - 1) * 32 + i] = zp;
            }
        }
        __syncthreads();

        // ---- P2: Ppred (128) || CN (128) ; t==0: M = C·P0 ; apred tail ----
        if (t > 0) {
            if (tid < 128) {
                float4 o0, o1;
                mm24(aug0 + r0*LDA + 32, aug0 + r1*LDA + 32, pAtr, LD, j4, o0, o1);
                int d0 = r0 - j4;
                if (d0 >= 0 && d0 < 4) ((float*)&o0)[d0] += qd[r0];
                int d1 = r1 - j4;
                if (d1 >= 0 && d1 < 4) ((float*)&o1)[d1] += qd[r1];
                *(float4*)(pPp + r0*LD + j4) = o0;
                *(float4*)(pPp + r1*LD + j4) = o1;
                *(float4*)(aug0 + r0*LDA + j4) = o0;
                *(float4*)(aug0 + r1*LDA + j4) = o1;
            } else if (tid < 256) {
                const int idx = tid - 128;
                const int ci = idx >> 3, cj = (idx & 7) << 2;
                float4 cn = mm4(pCm + ci*LD, aug0 + 32, LDA, cj);
                *(float4*)(tmpM + ci*LD + cj) = cn;
            }
        } else {
            if (tid < 128) {
                const int i = tid >> 3;
                float4 m = mm4(pCm + i*LD, pPp, LD, j4);
                *(float4*)(pCPm + i*LD + j4) = m;
                *(float4*)(augS0 + i*LDS2 + 16 + j4) = m;
            }
        }
        if (tid >= 480 && tid < 496) {
            const int i = tid - 480;
            float4 s4 = make_float4(0.f,0.f,0.f,0.f);
            #pragma unroll
            for (int k0 = 0; k0 < 32; k0 += 4) {
                float4 m4 = *(const float4*)(pCm + i * LD + k0);
                float4 v4 = *(const float4*)(zm2 + k0);
                FMA4L(s4, m4, v4);
            }
            apred[i] = (s4.x + s4.y) + (s4.z + s4.w);
        }
        __syncthreads();

        // ---- GJ loop: Y-solve (8 phases, thr<256) with S-build/S-solve/dz/P13
        //      hidden on threads 256+ ----
        {
            float* Ys = aug0; float* Yd = aug1;
            const int yi  = tid >> 3;
            const int yjA = (tid & 7) << 2;
            const int yjB = yjA + 32;
            #pragma unroll
            for (int pp = 0; pp < 8; ++pp) {
                if (tid < 256) {
                    if (t > 0) {
                        GJ4 s = gj4_pre(Ys, yi, pp << 2, LDA);
                        float4 EB = gj4_col4(s, Ys, yjB, LDA);
                        if (pp < 7) {
                            float4 EA = gj4_col4(s, Ys, yjA, LDA);
                            *(float4*)(Yd + yi * LDA + yjA) = EA;
                            *(float4*)(Yd + yi * LDA + yjB) = EB;
                        } else {
                            *(float4*)(g_Y + (ib-1)*1024 + yi*32 + (yjB-32)) = EB;
                        }
                    }
                } else {
                    const int idx = tid - 256;
                    if (pp == 0) {
                        // S-build + prefetch stores
                        if (t > 0) {
                            if (idx < 128) {
                                const int i = idx >> 3, jj = (idx & 7) << 2;
                                float4 m = mm4(tmpM + i*LD, pAtr, LD, jj);
                                float4 c4 = *(const float4*)(pCm + i*LD + jj);
                                float4 q4 = *(const float4*)(qd + jj);
                                m.x = fmaf(c4.x, q4.x, m.x); m.y = fmaf(c4.y, q4.y, m.y);
                                m.z = fmaf(c4.z, q4.z, m.z); m.w = fmaf(c4.w, q4.w, m.w);
                                *(float4*)(pCPm + i*LD + jj) = m;
                                *(float4*)(augS0 + i*LDS2 + 16 + jj) = m;
                            } else if (idx < 192) {
                                const int k = idx - 128;
                                const int i = k >> 2, jj = (k & 3) << 2;
                                float4 s = mm4(tmpM + i*LD, CAtr, LDCT, jj);
                                float4 cq = *(const float4*)(CQC + i*LDCT + jj);
                                s.x += cq.x; s.y += cq.y; s.z += cq.z; s.w += cq.w;
                                int d = i - jj;
                                if (d >= 0 && d < 4) ((float*)&s)[d] += rd[i];
                                *(float4*)(augS0 + i*LDS2 + jj) = s;
                            }
                        } else {
                            if (idx < 64) {
                                const int i = idx >> 2, jj = (idx & 3) << 2;
                                float4 s = mm4(pCPm + i*LD, pCtr, LDCT, jj);
                                int d = i - jj;
                                if (d >= 0 && d < 4) ((float*)&s)[d] += rd[i];
                                *(float4*)(augS0 + i*LDS2 + jj) = s;
                            }
                        }
                        if (hasnext) {
                            if (tid >= 448 && tid < 456) alB[nb*8  + (tid-448)] = pfa;
                            if (tid >= 456 && tid < 472) saB[nb*16 + (tid-456)] = pfo;
                            if (tid >= 472 && tid < 504) suB[nb*32 + (tid-472)] = pfu;
                        }
                    } else if (pp <= 4) {
                        const int pivot = pp - 1;
                        if (idx < 192) {
                            const int si = idx & 15;
                            const int sj = (idx >> 4) << 2;
                            float* Ss = (pivot & 1) ? augS1 : augS0;
                            float* Sd = (pivot & 1) ? augS0 : augS1;
                            if (pivot < 3 || sj >= 16) {
                                GJ4 s = gj4_pre(Ss, si, pivot << 2, LDS2);
                                float4 E = gj4_col4(s, Ss, sj, LDS2);
                                if (pivot < 3) {
                                    *(float4*)(Sd + si * LDS2 + sj) = E;
                                } else {
                                    KT2[(sj-16+0)*LDK + si] = E.x;
                                    KT2[(sj-16+1)*LDK + si] = E.y;
                                    KT2[(sj-16+2)*LDK + si] = E.z;
                                    KT2[(sj-16+3)*LDK + si] = E.w;
                                }
                            }
                        }
                        if (pp == 2 && tid >= 448 && tid < 464) {
                            const int j = tid - 448;
                            dz[j] = saB[pb * 16 + j] - apred[j];
                        }
                    } else if (pp == 5) {
                        const size_t ob = ib * 2112;
                        if (idx < 128) {
                            const int rr0 = idx >> 3, rr1 = rr0 + 16;
                            const int jj = (idx & 7) << 2;
                            float4 acc0 = *(const float4*)(pPp + rr0*LD + jj);
                            float4 acc1 = *(const float4*)(pPp + rr1*LD + jj);
                            #pragma unroll
                            for (int rr = 0; rr < 16; rr += 4) {
                                float4 k0 = *(const float4*)(KT2 + rr0*LDK + rr);
                                float4 k1 = *(const float4*)(KT2 + rr1*LDK + rr);
                                float4 m;
                                m = *(const float4*)(pCPm + (rr+0)*LD + jj);
                                acc0 = f4fma(-k0.x, m, acc0); acc1 = f4fma(-k1.x, m, acc1);
                                m = *(const float4*)(pCPm + (rr+1)*LD + jj);
                                acc0 = f4fma(-k0.y, m, acc0); acc1 = f4fma(-k1.y, m, acc1);
                                m = *(const float4*)(pCPm + (rr+2)*LD + jj);
                                acc0 = f4fma(-k0.z, m, acc0); acc1 = f4fma(-k1.z, m, acc1);
                                m = *(const float4*)(pCPm + (rr+3)*LD + jj);
                                acc0 = f4fma(-k0.w, m, acc0); acc1 = f4fma(-k1.w, m, acc1);
                            }
                            *(float4*)(zc + rr0*LD + jj) = acc0;
                            *(float4*)(zc + rr1*LD + jj) = acc1;
                            *(float4*)(out + ob + 32 + rr0*32 + jj) = acc0;
                            *(float4*)(out + ob + 32 + rr1*32 + jj) = acc1;
                            if (t == TLEN - 1) {
                                *(float4*)(out + ob + 1088 + rr0*32 + jj) = acc0;
                                *(float4*)(out + ob + 1088 + rr1*32 + jj) = acc1;
                            }
                        } else if (tid >= 480) {
                            const int i = tid - 480;
                            float4 s4 = make_float4(0.f,0.f,0.f,0.f);
                            #pragma unroll
                            for (int rr = 0; rr < 16; rr += 4) {
                                float4 k4 = *(const float4*)(KT2 + i * LDK + rr);
                                float4 d4 = *(const float4*)(dz + rr);
                                FMA4L(s4, k4, d4);
                            }
                            float nm = zm2[i] + (s4.x + s4.y) + (s4.z + s4.w);
                            zm[i] = nm;
                            out[ob + i] = nm;
                            if (t == TLEN - 1) out[ob + 1056 + i] = nm;
                        }
                    }
                }
                { float* w = Ys; Ys = Yd; Yd = w; }
                if (pp < 7) __syncthreads();
            }
        }
        // no trailing barrier: next P0-end barrier orders zc/zm/aug reuse
    }

    // =============== BACKWARD RTS SMOOTHER (2 phases/step) ===============
    __syncthreads();
    {   // preload slot TLEN-2 into parity 0
        const size_t slot0 = (size_t)b * TLEN + (TLEN - 2);
        if (tid < 256) {
            float4 y = *(const float4*)(g_Y  + slot0 * 1024 + i4 * 32 + j4);
            float4 n = *(const float4*)(g_Nm + slot0 * 1024 + i4 * 32 + j4);
            *(float4*)(Ybuf + i4 * LD + j4) = y;
            YtrB[(j4+0)*LD + i4] = y.x; YtrB[(j4+1)*LD + i4] = y.y;
            YtrB[(j4+2)*LD + i4] = y.z; YtrB[(j4+3)*LD + i4] = y.w;
            *(float4*)(NbS + i4 * LD + j4) = n;
            *(float4*)(fcS + i4 * LD + j4) =
                *(const float4*)(out + slot0 * 2112 + 32 + i4 * 32 + j4);
        }
        if (tid < 32) {
            zpS[tid] = g_zp[slot0 * 32 + tid];
            fmS[tid] = out[slot0 * 2112 + tid];
        }
    }
    __syncthreads();

    #pragma unroll 1
    for (int t = TLEN - 2; t >= 0; --t) {
        const size_t ib = (size_t)b * TLEN + t;
        const size_t ob = ib * 2112;
        const int pb = t & 1;
        const int nb = pb ^ 1;
        const bool hasprev = (t > 0);

        float4 pfY = make_float4(0.f,0.f,0.f,0.f);
        float4 pfN = make_float4(0.f,0.f,0.f,0.f);
        float4 pfc = make_float4(0.f,0.f,0.f,0.f);
        float pfz = 0.f, pfm = 0.f;
        int pi = 0, pj = 0;
        if (tid >= 256) { const int idx = tid - 256; pi = idx >> 3; pj = (idx & 7) << 2; }
        if (hasprev) {
            const size_t sp = ib - 1;
            if (tid >= 256) {
                pfY = *(const float4*)(g_Y  + sp * 1024 + pi * 32 + pj);
                pfN = *(const float4*)(g_Nm + sp * 1024 + pi * 32 + pj);
                pfc = *(const float4*)(out + sp * 2112 + 32 + pi * 32 + pj);
            }
            if (tid >= 448 && tid < 480) {
                pfz = g_zp[sp * 32 + (tid - 448)];
                pfm = out[sp * 2112 + (tid - 448)];
            }
        }

        // ---- PW: W = Ps·Y - N (128 thr) ; zs2 (warp 15) ----
        if (tid < 128) {
            float4 o0, o1;
            mm24(zc + r0*LD, zc + r1*LD, Ybuf + pb*1152, LD, j4, o0, o1);
            float4 n0 = *(const float4*)(NbS + pb*1152 + r0*LD + j4);
            float4 n1 = *(const float4*)(NbS + pb*1152 + r1*LD + j4);
            o0.x -= n0.x; o0.y -= n0.y; o0.z -= n0.z; o0.w -= n0.w;
            o1.x -= n1.x; o1.y -= n1.y; o1.z -= n1.z; o1.w -= n1.w;
            *(float4*)(aug1 + r0*LDA + j4) = o0;
            *(float4*)(aug1 + r1*LDA + j4) = o1;
        } else if (tid >= 480) {
            const int i = tid - 480;
            float4 s4 = make_float4(0.f,0.f,0.f,0.f);
            #pragma unroll
            for (int k0 = 0; k0 < 32; k0 += 4) {
                float4 y4 = *(const float4*)(YtrB + pb*1152 + i*LD + k0);
                float4 z4 = *(const float4*)(zm + k0);
                float4 p4 = *(const float4*)(zpS + pb*32 + k0);
                float4 d4 = make_float4(z4.x-p4.x, z4.y-p4.y, z4.z-p4.z, z4.w-p4.w);
                FMA4L(s4, y4, d4);
            }
            zm2[i] = fmS[pb*32 + i] + (s4.x + s4.y) + (s4.z + s4.w);
        }
        __syncthreads();

        // ---- P21: Ps = fc + Ytr·W ; outputs ; store prefetch [nb] ----
        if (tid < 128) {
            float4 w0, w1;
            mm24(YtrB + pb*1152 + r0*LD, YtrB + pb*1152 + r1*LD, aug1, LDA, j4, w0, w1);
            float4 f0 = *(const float4*)(fcS + pb*1152 + r0*LD + j4);
            float4 f1 = *(const float4*)(fcS + pb*1152 + r1*LD + j4);
            f0.x += w0.x; f0.y += w0.y; f0.z += w0.z; f0.w += w0.w;
            f1.x += w1.x; f1.y += w1.y; f1.z += w1.z; f1.w += w1.w;
            *(float4*)(zc + r0*LD + j4) = f0;
            *(float4*)(zc + r1*LD + j4) = f1;
            *(float4*)(out + ob + 1088 + r0*32 + j4) = f0;
            *(float4*)(out + ob + 1088 + r1*32 + j4) = f1;
        }
        if (tid >= 256 && hasprev) {
            *(float4*)(Ybuf + nb*1152 + pi*LD + pj) = pfY;
            YtrB[nb*1152 + (pj+0)*LD + pi] = pfY.x;
            YtrB[nb*1152 + (pj+1)*LD + pi] = pfY.y;
            YtrB[nb*1152 + (pj+2)*LD + pi] = pfY.z;
            YtrB[nb*1152 + (pj+3)*LD + pi] = pfY.w;
            *(float4*)(NbS + nb*1152 + pi*LD + pj) = pfN;
            *(float4*)(fcS + nb*1152 + pi*LD + pj) = pfc;
        }
        if (tid >= 448 && tid < 480) {
            const int i = tid - 448;
            float nm = zm2[i];
            zm[i] = nm;
            out[ob + 1056 + i] = nm;
            if (hasprev) {
                zpS[nb*32 + i] = pfz;
                fmS[nb*32 + i] = pfm;
            }
        }
        __syncthreads();
    }
}

extern "C" void kernel_launch(void* const* d_in, const int* in_sizes, int n_in,
                              void* d_out, int out_size) {
    const float* g_a    = (const float*)d_in[0];
    const float* g_alpha= (const float*)d_in[1];
    const float* g_u    = (const float*)d_in[2];
    const float* g_A    = (const float*)d_in[3];
    const float* g_B    = (const float*)d_in[4];
    const float* g_C    = (const float*)d_in[5];
    const float* g_lQ   = (const float*)d_in[6];
    const float* g_lR   = (const float*)d_in[7];
    const float* g_z0m  = (const float*)d_in[8];
    const float* g_z0lv = (const float*)d_in[9];
    float* out = (float*)d_out;
    int B = in_sizes[0] / (TLEN * 16);
    size_t smem = SMEM_FLOATS * sizeof(float);
    cudaFuncSetAttribute(lgssm_kernel, cudaFuncAttributeMaxDynamicSharedMemorySize, (int)smem);
    lgssm_kernel<<<B, NT, smem>>>(g_a, g_alpha, g_u, g_A, g_B, g_C,
                                  g_lQ, g_lR, g_z0m, g_z0lv, out);
}